// round 1
// baseline (speedup 1.0000x reference)
#include <cuda_runtime.h>
#include <math.h>

#define Bsz  4
#define Cdim 256
#define Ddim 128
#define Nn   4096

// Scratch (static __device__ — no allocations allowed)
__device__ float g_Q[Bsz * Nn * Ddim];
__device__ float g_K[Bsz * Nn * Ddim];
__device__ float g_V[Bsz * Nn * Ddim];
__device__ float g_Y[Bsz * Nn * Ddim];

// ---------------------------------------------------------------------------
// Kernel 1: fused QKV projection.
// out[r][n] = sum_c W[r][c] * x[b][c][n], written transposed into
// Q/K/V[b][n][dd] (n-major, d contiguous) for attention-friendly loads.
// Tiled SGEMM: BM=64 (proj rows), BN=64 (pixels), BK=16, 256 thr, 4x4 micro.
// ---------------------------------------------------------------------------
__global__ void qkv_kernel(const float* __restrict__ x,
                           const float* __restrict__ wt,
                           const float* __restrict__ wp,
                           const float* __restrict__ wg) {
    __shared__ float As[64][17];   // [m][k]
    __shared__ float Bs[16][64];   // [k][n]
    const int b  = blockIdx.z;
    const int n0 = blockIdx.x * 64;
    const int r0 = blockIdx.y * 64;

    const float* W;
    float* dst;
    if (r0 < 128)      { W = wt; dst = g_Q; }
    else if (r0 < 256) { W = wp; dst = g_K; }
    else               { W = wg; dst = g_V; }
    const int rl0 = r0 & 127;

    const float* xb = x + (size_t)b * Cdim * Nn;
    float* db = dst + (size_t)b * Nn * Ddim;

    const int tid = threadIdx.x;
    const int tx = tid & 15, ty = tid >> 4;

    float acc[4][4] = {};
    for (int k0 = 0; k0 < Cdim; k0 += 16) {
        #pragma unroll
        for (int i = 0; i < 4; i++) {
            int f = tid + i * 256;
            int m = f >> 4, k = f & 15;
            As[m][k] = W[(rl0 + m) * Cdim + k0 + k];
        }
        #pragma unroll
        for (int i = 0; i < 4; i++) {
            int f = tid + i * 256;
            int k = f >> 6, n = f & 63;
            Bs[k][n] = xb[(size_t)(k0 + k) * Nn + n0 + n];
        }
        __syncthreads();
        #pragma unroll
        for (int k = 0; k < 16; k++) {
            float a[4], bv[4];
            #pragma unroll
            for (int i = 0; i < 4; i++) a[i] = As[ty * 4 + i][k];
            #pragma unroll
            for (int j = 0; j < 4; j++) bv[j] = Bs[k][tx * 4 + j];
            #pragma unroll
            for (int i = 0; i < 4; i++)
                #pragma unroll
                for (int j = 0; j < 4; j++)
                    acc[i][j] = fmaf(a[i], bv[j], acc[i][j]);
        }
        __syncthreads();
    }
    #pragma unroll
    for (int i = 0; i < 4; i++)
        #pragma unroll
        for (int j = 0; j < 4; j++)
            db[(size_t)(n0 + tx * 4 + j) * Ddim + rl0 + ty * 4 + i] = acc[i][j];
}

// ---------------------------------------------------------------------------
// Kernel 2: fp32 flash attention.
// Per block: one (batch b, 64-query tile). Online softmax over all 64 key
// tiles. Q [64][132] / V [64][132] / P [64][68] in SMEM, K stored transposed
// [128][68] so the S-GEMM reads are conflict-free float4s.
// Thread layout 16x16, each thread owns a 4x4 S micro-tile (rows=4ty+i,
// cols=4tx+j) and an O fragment of 4 rows x 8 cols (d = h*64 + 4tx + c).
// ---------------------------------------------------------------------------
#define ATTN_SMEM ((64 * 132 + 128 * 68 + 64 * 132 + 64 * 68) * 4)

__global__ void attn_kernel() {
    extern __shared__ float sm[];
    float* Qs  = sm;                 // [64][132]
    float* Kst = Qs + 64 * 132;      // [128][68]  (transposed K)
    float* Vs  = Kst + 128 * 68;     // [64][132]
    float* Ps  = Vs + 64 * 132;      // [64][68]

    const int b  = blockIdx.y;
    const int q0 = blockIdx.x * 64;
    const float* Qg = g_Q + ((size_t)b * Nn + q0) * Ddim;
    const float* Kg = g_K + (size_t)b * Nn * Ddim;
    const float* Vg = g_V + (size_t)b * Nn * Ddim;
    float*       Yg = g_Y + (size_t)b * Nn * Ddim;

    const int tid = threadIdx.x;
    const int tx = tid & 15, ty = tid >> 4;

    // Load Q tile once (64 rows x 128, coalesced float4)
    #pragma unroll
    for (int i = 0; i < 8; i++) {
        int f = tid + i * 256;
        int r = f >> 5, c4 = (f & 31) * 4;
        float4 v = *(const float4*)&Qg[r * Ddim + c4];
        *(float4*)&Qs[r * 132 + c4] = v;
    }

    float m_i[4], l_i[4];
    float o[4][2][4];
    #pragma unroll
    for (int i = 0; i < 4; i++) {
        m_i[i] = -1e30f; l_i[i] = 0.f;
        #pragma unroll
        for (int h = 0; h < 2; h++)
            #pragma unroll
            for (int c = 0; c < 4; c++) o[i][h][c] = 0.f;
    }

    for (int j0 = 0; j0 < Nn; j0 += 64) {
        __syncthreads();  // protect prior tile's Kst/Vs/Ps reads (also covers Q store)
        // Load K (transposed into Kst) and V
        #pragma unroll
        for (int i = 0; i < 8; i++) {
            int f = tid + i * 256;
            int r = f >> 5, c4 = (f & 31) * 4;
            float4 kv = *(const float4*)&Kg[(size_t)(j0 + r) * Ddim + c4];
            Kst[(c4 + 0) * 68 + r] = kv.x;
            Kst[(c4 + 1) * 68 + r] = kv.y;
            Kst[(c4 + 2) * 68 + r] = kv.z;
            Kst[(c4 + 3) * 68 + r] = kv.w;
            float4 vv = *(const float4*)&Vg[(size_t)(j0 + r) * Ddim + c4];
            *(float4*)&Vs[r * 132 + c4] = vv;
        }
        __syncthreads();

        // S = Q K^T (64x64 tile; 4x4 per thread)
        float s[4][4] = {};
        #pragma unroll 2
        for (int dd = 0; dd < Ddim; dd += 4) {
            float q[4][4], kk[4][4];
            #pragma unroll
            for (int i = 0; i < 4; i++)
                *(float4*)&q[i][0] = *(const float4*)&Qs[(ty * 4 + i) * 132 + dd];
            #pragma unroll
            for (int ds = 0; ds < 4; ds++)
                *(float4*)&kk[ds][0] = *(const float4*)&Kst[(dd + ds) * 68 + tx * 4];
            #pragma unroll
            for (int i = 0; i < 4; i++)
                #pragma unroll
                for (int ds = 0; ds < 4; ds++)
                    #pragma unroll
                    for (int jj = 0; jj < 4; jj++)
                        s[i][jj] = fmaf(q[i][ds], kk[ds][jj], s[i][jj]);
        }

        // Online softmax. The 16 threads sharing a row are lanes [0..15] or
        // [16..31] of a warp -> width-16 xor shuffles reduce within the row.
        #pragma unroll
        for (int i = 0; i < 4; i++) {
            float mx = fmaxf(fmaxf(s[i][0], s[i][1]), fmaxf(s[i][2], s[i][3]));
            #pragma unroll
            for (int off = 8; off > 0; off >>= 1)
                mx = fmaxf(mx, __shfl_xor_sync(0xffffffffu, mx, off, 16));
            float mnew  = fmaxf(m_i[i], mx);
            float scale = __expf(m_i[i] - mnew);
            m_i[i] = mnew;
            l_i[i] *= scale;
            #pragma unroll
            for (int h = 0; h < 2; h++)
                #pragma unroll
                for (int c = 0; c < 4; c++) o[i][h][c] *= scale;
            float rs = 0.f;
            #pragma unroll
            for (int jj = 0; jj < 4; jj++) {
                float p = __expf(s[i][jj] - mnew);
                s[i][jj] = p;
                rs += p;
            }
            #pragma unroll
            for (int off = 8; off > 0; off >>= 1)
                rs += __shfl_xor_sync(0xffffffffu, rs, off, 16);
            l_i[i] += rs;
            *(float4*)&Ps[(ty * 4 + i) * 68 + tx * 4] =
                make_float4(s[i][0], s[i][1], s[i][2], s[i][3]);
        }
        __syncthreads();

        // O += P * V   (each thread: 4 rows x (2x4) d-cols)
        #pragma unroll 4
        for (int k = 0; k < 64; k++) {
            float p[4];
            #pragma unroll
            for (int i = 0; i < 4; i++) p[i] = Ps[(ty * 4 + i) * 68 + k];
            float4 v0 = *(const float4*)&Vs[k * 132 + tx * 4];
            float4 v1 = *(const float4*)&Vs[k * 132 + 64 + tx * 4];
            #pragma unroll
            for (int i = 0; i < 4; i++) {
                o[i][0][0] = fmaf(p[i], v0.x, o[i][0][0]);
                o[i][0][1] = fmaf(p[i], v0.y, o[i][0][1]);
                o[i][0][2] = fmaf(p[i], v0.z, o[i][0][2]);
                o[i][0][3] = fmaf(p[i], v0.w, o[i][0][3]);
                o[i][1][0] = fmaf(p[i], v1.x, o[i][1][0]);
                o[i][1][1] = fmaf(p[i], v1.y, o[i][1][1]);
                o[i][1][2] = fmaf(p[i], v1.z, o[i][1][2]);
                o[i][1][3] = fmaf(p[i], v1.w, o[i][1][3]);
            }
        }
    }

    // Normalize and write y[b][n][dd]
    #pragma unroll
    for (int i = 0; i < 4; i++) {
        float inv = 1.f / l_i[i];
        float4 w0 = make_float4(o[i][0][0] * inv, o[i][0][1] * inv,
                                o[i][0][2] * inv, o[i][0][3] * inv);
        float4 w1 = make_float4(o[i][1][0] * inv, o[i][1][1] * inv,
                                o[i][1][2] * inv, o[i][1][3] * inv);
        size_t row = (size_t)(q0 + ty * 4 + i) * Ddim;
        *(float4*)&Yg[row + tx * 4]      = w0;
        *(float4*)&Yg[row + 64 + tx * 4] = w1;
    }
}

// ---------------------------------------------------------------------------
// Kernel 3: out = x + w_out * y   (C=256 x d=128 GEMM per pixel + residual)
// BM=64 (c), BN=64 (n), BK=16, both operands loaded [row][k].
// ---------------------------------------------------------------------------
__global__ void out_kernel(const float* __restrict__ x,
                           const float* __restrict__ wo,
                           float* __restrict__ out) {
    __shared__ float As[64][17];   // w_out [c][k]
    __shared__ float Bs[64][17];   // y     [n][k]
    const int b  = blockIdx.z;
    const int n0 = blockIdx.x * 64;
    const int c0 = blockIdx.y * 64;
    const float* Yb = g_Y + (size_t)b * Nn * Ddim;
    const int tid = threadIdx.x;
    const int tx = tid & 15, ty = tid >> 4;

    float acc[4][4] = {};
    for (int k0 = 0; k0 < Ddim; k0 += 16) {
        #pragma unroll
        for (int i = 0; i < 4; i++) {
            int f = tid + i * 256;
            int m = f >> 4, k = f & 15;
            As[m][k] = wo[(c0 + m) * Ddim + k0 + k];
            Bs[m][k] = Yb[(size_t)(n0 + m) * Ddim + k0 + k];
        }
        __syncthreads();
        #pragma unroll
        for (int k = 0; k < 16; k++) {
            float a[4], bv[4];
            #pragma unroll
            for (int i = 0; i < 4; i++) a[i] = As[ty * 4 + i][k];
            #pragma unroll
            for (int j = 0; j < 4; j++) bv[j] = Bs[tx * 4 + j][k];
            #pragma unroll
            for (int i = 0; i < 4; i++)
                #pragma unroll
                for (int j = 0; j < 4; j++)
                    acc[i][j] = fmaf(a[i], bv[j], acc[i][j]);
        }
        __syncthreads();
    }
    #pragma unroll
    for (int i = 0; i < 4; i++)
        #pragma unroll
        for (int j = 0; j < 4; j++) {
            size_t idx = (size_t)b * Cdim * Nn +
                         (size_t)(c0 + ty * 4 + i) * Nn + n0 + tx * 4 + j;
            out[idx] = x[idx] + acc[i][j];
        }
}

// ---------------------------------------------------------------------------
extern "C" void kernel_launch(void* const* d_in, const int* in_sizes, int n_in,
                              void* d_out, int out_size) {
    const float* x  = (const float*)d_in[0];
    const float* wt = (const float*)d_in[1];
    const float* wp = (const float*)d_in[2];
    const float* wg = (const float*)d_in[3];
    const float* wo = (const float*)d_in[4];
    float* out = (float*)d_out;

    cudaFuncSetAttribute(attn_kernel,
                         cudaFuncAttributeMaxDynamicSharedMemorySize, ATTN_SMEM);

    qkv_kernel<<<dim3(Nn / 64, 6, Bsz), 256>>>(x, wt, wp, wg);
    attn_kernel<<<dim3(Nn / 64, Bsz), 256, ATTN_SMEM>>>();
    out_kernel<<<dim3(Nn / 64, Cdim / 64, Bsz), 256>>>(x, wo, out);
}

// round 3
// speedup vs baseline: 2.3126x; 2.3126x over previous
#include <cuda_runtime.h>
#include <cstdint>
#include <math.h>

#define Bsz  4
#define Cdim 256
#define Ddim 128
#define Nn   4096

// Scratch (static __device__ — no allocations allowed)
__device__ float g_Q[Bsz * Nn * Ddim];
__device__ float g_K[Bsz * Nn * Ddim];
__device__ float g_V[Bsz * Nn * Ddim];
__device__ float g_Y[Bsz * Nn * Ddim];

// ---------------------------------------------------------------------------
// Kernel 1: fused QKV projection (unchanged from R0).
// ---------------------------------------------------------------------------
__global__ void qkv_kernel(const float* __restrict__ x,
                           const float* __restrict__ wt,
                           const float* __restrict__ wp,
                           const float* __restrict__ wg) {
    __shared__ float As[64][17];
    __shared__ float Bs[16][64];
    const int b  = blockIdx.z;
    const int n0 = blockIdx.x * 64;
    const int r0 = blockIdx.y * 64;

    const float* W;
    float* dst;
    if (r0 < 128)      { W = wt; dst = g_Q; }
    else if (r0 < 256) { W = wp; dst = g_K; }
    else               { W = wg; dst = g_V; }
    const int rl0 = r0 & 127;

    const float* xb = x + (size_t)b * Cdim * Nn;
    float* db = dst + (size_t)b * Nn * Ddim;

    const int tid = threadIdx.x;
    const int tx = tid & 15, ty = tid >> 4;

    float acc[4][4] = {};
    for (int k0 = 0; k0 < Cdim; k0 += 16) {
        #pragma unroll
        for (int i = 0; i < 4; i++) {
            int f = tid + i * 256;
            int m = f >> 4, k = f & 15;
            As[m][k] = W[(rl0 + m) * Cdim + k0 + k];
        }
        #pragma unroll
        for (int i = 0; i < 4; i++) {
            int f = tid + i * 256;
            int k = f >> 6, n = f & 63;
            Bs[k][n] = xb[(size_t)(k0 + k) * Nn + n0 + n];
        }
        __syncthreads();
        #pragma unroll
        for (int k = 0; k < 16; k++) {
            float a[4], bv[4];
            #pragma unroll
            for (int i = 0; i < 4; i++) a[i] = As[ty * 4 + i][k];
            #pragma unroll
            for (int j = 0; j < 4; j++) bv[j] = Bs[k][tx * 4 + j];
            #pragma unroll
            for (int i = 0; i < 4; i++)
                #pragma unroll
                for (int j = 0; j < 4; j++)
                    acc[i][j] = fmaf(a[i], bv[j], acc[i][j]);
        }
        __syncthreads();
    }
    #pragma unroll
    for (int i = 0; i < 4; i++)
        #pragma unroll
        for (int j = 0; j < 4; j++)
            db[(size_t)(n0 + tx * 4 + j) * Ddim + rl0 + ty * 4 + i] = acc[i][j];
}

// ---------------------------------------------------------------------------
// Kernel 2: flash attention on tensor cores (mma.sync m16n8k8 tf32).
// S = Q K^T uses tf32 hi/lo split (3 MMAs) => ~fp32-accurate scores.
// P V uses plain tf32 (P in [0,1], error diluted by residual).
// Block: 128 queries, 8 warps (warp w owns rows w*16..w*16+15).
// Key tile: 64. Khi/Klo pre-split in SMEM; V pre-rounded to tf32;
// P staged via SMEM (C-frag layout -> A-frag layout).
// ---------------------------------------------------------------------------
#define QS_STR 132
#define KS_STR 132
#define VS_STR 136
#define PS_STR 68
#define ATTN_SMEM ((128 * QS_STR + 2 * 64 * KS_STR + 64 * VS_STR + 128 * PS_STR) * 4)

__device__ __forceinline__ uint32_t f2tf(float x) {
    uint32_t r;
    asm("cvt.rna.tf32.f32 %0, %1;" : "=r"(r) : "f"(x));
    return r;
}

__device__ __forceinline__ void mma8(float* c, const uint32_t* a, const uint32_t* b) {
    asm volatile(
        "mma.sync.aligned.m16n8k8.row.col.f32.tf32.tf32.f32 "
        "{%0,%1,%2,%3},{%4,%5,%6,%7},{%8,%9},{%0,%1,%2,%3};"
        : "+f"(c[0]), "+f"(c[1]), "+f"(c[2]), "+f"(c[3])
        : "r"(a[0]), "r"(a[1]), "r"(a[2]), "r"(a[3]), "r"(b[0]), "r"(b[1]));
}

__global__ void __launch_bounds__(256, 1) attn_kernel() {
    extern __shared__ float sm[];
    float* Qs = sm;                       // [128][132] raw f32
    float* Kh = Qs + 128 * QS_STR;        // [64][132] tf32 hi
    float* Kl = Kh + 64 * KS_STR;         // [64][132] tf32 lo
    float* Vs = Kl + 64 * KS_STR;         // [64][136] tf32
    float* Ps = Vs + 64 * VS_STR;         // [128][68] tf32

    const int b  = blockIdx.y;
    const int q0 = blockIdx.x * 128;
    const float* Qg = g_Q + ((size_t)b * Nn + q0) * Ddim;
    const float* Kg = g_K + (size_t)b * Nn * Ddim;
    const float* Vg = g_V + (size_t)b * Nn * Ddim;
    float*       Yg = g_Y + (size_t)b * Nn * Ddim;

    const int tid  = threadIdx.x;
    const int lane = tid & 31;
    const int w    = tid >> 5;
    const int g    = lane >> 2;   // 0..7
    const int t    = lane & 3;    // 0..3

    // Load Q tile once (raw f32)
    #pragma unroll
    for (int i = 0; i < 16; i++) {
        int f = tid + i * 256;
        int r = f >> 5, c4 = (f & 31) * 4;
        *(float4*)&Qs[r * QS_STR + c4] = *(const float4*)&Qg[r * Ddim + c4];
    }

    float m0 = -1e30f, m1 = -1e30f, l0 = 0.f, l1 = 0.f;
    float o[16][4];
    #pragma unroll
    for (int nb = 0; nb < 16; nb++)
        #pragma unroll
        for (int c = 0; c < 4; c++) o[nb][c] = 0.f;

    const int row0 = w * 16 + g;
    const int row1 = row0 + 8;

    for (int j0 = 0; j0 < Nn; j0 += 64) {
        __syncthreads();   // previous iteration's Kh/Kl/Vs reads done (covers Q too)
        // Load + split K, load + round V
        #pragma unroll
        for (int i = 0; i < 8; i++) {
            int f = tid + i * 256;
            int r = f >> 5, c4 = (f & 31) * 4;
            float4 kv = *(const float4*)&Kg[(size_t)(j0 + r) * Ddim + c4];
            float4 hv, lv;
            hv.x = __uint_as_float(f2tf(kv.x)); lv.x = __uint_as_float(f2tf(kv.x - hv.x));
            hv.y = __uint_as_float(f2tf(kv.y)); lv.y = __uint_as_float(f2tf(kv.y - hv.y));
            hv.z = __uint_as_float(f2tf(kv.z)); lv.z = __uint_as_float(f2tf(kv.z - hv.z));
            hv.w = __uint_as_float(f2tf(kv.w)); lv.w = __uint_as_float(f2tf(kv.w - hv.w));
            *(float4*)&Kh[r * KS_STR + c4] = hv;
            *(float4*)&Kl[r * KS_STR + c4] = lv;
            float4 vv = *(const float4*)&Vg[(size_t)(j0 + r) * Ddim + c4];
            vv.x = __uint_as_float(f2tf(vv.x));
            vv.y = __uint_as_float(f2tf(vv.y));
            vv.z = __uint_as_float(f2tf(vv.z));
            vv.w = __uint_as_float(f2tf(vv.w));
            *(float4*)&Vs[r * VS_STR + c4] = vv;
        }
        __syncthreads();

        // ---- S = Q K^T (split tf32: qh*kh + qh*kl + ql*kh) ----
        float s[8][4];
        #pragma unroll
        for (int nb = 0; nb < 8; nb++)
            #pragma unroll
            for (int c = 0; c < 4; c++) s[nb][c] = 0.f;

        #pragma unroll
        for (int kb = 0; kb < 16; kb++) {
            const int kc = kb * 8 + t;
            float a0 = Qs[row0 * QS_STR + kc];
            float a1 = Qs[row1 * QS_STR + kc];
            float a2 = Qs[row0 * QS_STR + kc + 4];
            float a3 = Qs[row1 * QS_STR + kc + 4];
            uint32_t ah[4], al[4];
            ah[0] = f2tf(a0); al[0] = f2tf(a0 - __uint_as_float(ah[0]));
            ah[1] = f2tf(a1); al[1] = f2tf(a1 - __uint_as_float(ah[1]));
            ah[2] = f2tf(a2); al[2] = f2tf(a2 - __uint_as_float(ah[2]));
            ah[3] = f2tf(a3); al[3] = f2tf(a3 - __uint_as_float(ah[3]));
            #pragma unroll
            for (int nb = 0; nb < 8; nb++) {
                const int krow = nb * 8 + g;
                uint32_t bh[2], bl[2];
                bh[0] = __float_as_uint(Kh[krow * KS_STR + kc]);
                bh[1] = __float_as_uint(Kh[krow * KS_STR + kc + 4]);
                bl[0] = __float_as_uint(Kl[krow * KS_STR + kc]);
                bl[1] = __float_as_uint(Kl[krow * KS_STR + kc + 4]);
                mma8(s[nb], ah, bh);
                mma8(s[nb], ah, bl);
                mma8(s[nb], al, bh);
            }
        }

        // ---- online softmax (rows row0 and row1; 4 lanes share a row) ----
        float mx0 = -1e30f, mx1 = -1e30f;
        #pragma unroll
        for (int nb = 0; nb < 8; nb++) {
            mx0 = fmaxf(mx0, fmaxf(s[nb][0], s[nb][1]));
            mx1 = fmaxf(mx1, fmaxf(s[nb][2], s[nb][3]));
        }
        mx0 = fmaxf(mx0, __shfl_xor_sync(0xffffffffu, mx0, 1));
        mx0 = fmaxf(mx0, __shfl_xor_sync(0xffffffffu, mx0, 2));
        mx1 = fmaxf(mx1, __shfl_xor_sync(0xffffffffu, mx1, 1));
        mx1 = fmaxf(mx1, __shfl_xor_sync(0xffffffffu, mx1, 2));
        float mn0 = fmaxf(m0, mx0), mn1 = fmaxf(m1, mx1);
        float sc0 = __expf(m0 - mn0), sc1 = __expf(m1 - mn1);
        m0 = mn0; m1 = mn1;
        l0 *= sc0; l1 *= sc1;
        #pragma unroll
        for (int nb = 0; nb < 16; nb++) {
            o[nb][0] *= sc0; o[nb][1] *= sc0;
            o[nb][2] *= sc1; o[nb][3] *= sc1;
        }
        float rs0 = 0.f, rs1 = 0.f;
        #pragma unroll
        for (int nb = 0; nb < 8; nb++) {
            float p0 = __expf(s[nb][0] - mn0);
            float p1 = __expf(s[nb][1] - mn0);
            float p2 = __expf(s[nb][2] - mn1);
            float p3 = __expf(s[nb][3] - mn1);
            rs0 += p0 + p1;
            rs1 += p2 + p3;
            // store pre-rounded tf32 P in C-frag position
            float2 hi = make_float2(__uint_as_float(f2tf(p0)), __uint_as_float(f2tf(p1)));
            float2 lo = make_float2(__uint_as_float(f2tf(p2)), __uint_as_float(f2tf(p3)));
            *(float2*)&Ps[row0 * PS_STR + nb * 8 + t * 2] = hi;
            *(float2*)&Ps[row1 * PS_STR + nb * 8 + t * 2] = lo;
        }
        rs0 += __shfl_xor_sync(0xffffffffu, rs0, 1);
        rs0 += __shfl_xor_sync(0xffffffffu, rs0, 2);
        rs1 += __shfl_xor_sync(0xffffffffu, rs1, 1);
        rs1 += __shfl_xor_sync(0xffffffffu, rs1, 2);
        l0 += rs0; l1 += rs1;
        __syncwarp();  // P rows are warp-private: order STS -> LDS within warp

        // ---- O += P V  (k = 64 keys, n = 128 dims) ----
        #pragma unroll
        for (int kb = 0; kb < 8; kb++) {
            const int kc = kb * 8 + t;
            uint32_t pa[4];
            pa[0] = __float_as_uint(Ps[row0 * PS_STR + kc]);
            pa[1] = __float_as_uint(Ps[row1 * PS_STR + kc]);
            pa[2] = __float_as_uint(Ps[row0 * PS_STR + kc + 4]);
            pa[3] = __float_as_uint(Ps[row1 * PS_STR + kc + 4]);
            #pragma unroll
            for (int nb = 0; nb < 16; nb++) {
                uint32_t vb[2];
                vb[0] = __float_as_uint(Vs[(kb * 8 + t) * VS_STR + nb * 8 + g]);
                vb[1] = __float_as_uint(Vs[(kb * 8 + t + 4) * VS_STR + nb * 8 + g]);
                mma8(o[nb], pa, vb);
            }
        }
    }

    // Normalize and write y[b][n][d]
    float inv0 = 1.f / l0, inv1 = 1.f / l1;
    #pragma unroll
    for (int nb = 0; nb < 16; nb++) {
        size_t r0o = (size_t)(q0 + row0) * Ddim + nb * 8 + t * 2;
        size_t r1o = (size_t)(q0 + row1) * Ddim + nb * 8 + t * 2;
        *(float2*)&Yg[r0o] = make_float2(o[nb][0] * inv0, o[nb][1] * inv0);
        *(float2*)&Yg[r1o] = make_float2(o[nb][2] * inv1, o[nb][3] * inv1);
    }
}

// ---------------------------------------------------------------------------
// Kernel 3: out = x + w_out * y (unchanged from R0).
// ---------------------------------------------------------------------------
__global__ void out_kernel(const float* __restrict__ x,
                           const float* __restrict__ wo,
                           float* __restrict__ out) {
    __shared__ float As[64][17];
    __shared__ float Bs[64][17];
    const int b  = blockIdx.z;
    const int n0 = blockIdx.x * 64;
    const int c0 = blockIdx.y * 64;
    const float* Yb = g_Y + (size_t)b * Nn * Ddim;
    const int tid = threadIdx.x;
    const int tx = tid & 15, ty = tid >> 4;

    float acc[4][4] = {};
    for (int k0 = 0; k0 < Ddim; k0 += 16) {
        #pragma unroll
        for (int i = 0; i < 4; i++) {
            int f = tid + i * 256;
            int m = f >> 4, k = f & 15;
            As[m][k] = wo[(c0 + m) * Ddim + k0 + k];
            Bs[m][k] = Yb[(size_t)(n0 + m) * Ddim + k0 + k];
        }
        __syncthreads();
        #pragma unroll
        for (int k = 0; k < 16; k++) {
            float a[4], bv[4];
            #pragma unroll
            for (int i = 0; i < 4; i++) a[i] = As[ty * 4 + i][k];
            #pragma unroll
            for (int j = 0; j < 4; j++) bv[j] = Bs[tx * 4 + j][k];
            #pragma unroll
            for (int i = 0; i < 4; i++)
                #pragma unroll
                for (int j = 0; j < 4; j++)
                    acc[i][j] = fmaf(a[i], bv[j], acc[i][j]);
        }
        __syncthreads();
    }
    #pragma unroll
    for (int i = 0; i < 4; i++)
        #pragma unroll
        for (int j = 0; j < 4; j++) {
            size_t idx = (size_t)b * Cdim * Nn +
                         (size_t)(c0 + ty * 4 + i) * Nn + n0 + tx * 4 + j;
            out[idx] = x[idx] + acc[i][j];
        }
}

// ---------------------------------------------------------------------------
extern "C" void kernel_launch(void* const* d_in, const int* in_sizes, int n_in,
                              void* d_out, int out_size) {
    const float* x  = (const float*)d_in[0];
    const float* wt = (const float*)d_in[1];
    const float* wp = (const float*)d_in[2];
    const float* wg = (const float*)d_in[3];
    const float* wo = (const float*)d_in[4];
    float* out = (float*)d_out;

    cudaFuncSetAttribute(attn_kernel,
                         cudaFuncAttributeMaxDynamicSharedMemorySize, ATTN_SMEM);

    qkv_kernel<<<dim3(Nn / 64, 6, Bsz), 256>>>(x, wt, wp, wg);
    attn_kernel<<<dim3(Nn / 128, Bsz), 256, ATTN_SMEM>>>();
    out_kernel<<<dim3(Nn / 64, Cdim / 64, Bsz), 256>>>(x, wo, out);
}

// round 4
// speedup vs baseline: 3.2299x; 1.3966x over previous
#include <cuda_runtime.h>
#include <cuda_bf16.h>
#include <cstdint>
#include <math.h>

#define Bsz  4
#define Cdim 256
#define Ddim 128
#define Nn   4096

// Scratch (static __device__ — no allocations allowed)
__device__ __nv_bfloat16 g_Qh[Bsz * Nn * Ddim];
__device__ __nv_bfloat16 g_Ql[Bsz * Nn * Ddim];
__device__ __nv_bfloat16 g_Kh[Bsz * Nn * Ddim];
__device__ __nv_bfloat16 g_Kl[Bsz * Nn * Ddim];
__device__ float g_V[Bsz * Nn * Ddim];   // tf32-pre-rounded
__device__ float g_Y[Bsz * Nn * Ddim];

__device__ __forceinline__ uint32_t f2tf(float x) {
    uint32_t r;
    asm("cvt.rna.tf32.f32 %0, %1;" : "=r"(r) : "f"(x));
    return r;
}

// ---------------------------------------------------------------------------
// Kernel 1: fused QKV projection. A tile transposed to [k][m] so both
// operand reads in the FMA loop are LDS.128. Epilogue writes Q/K as
// bf16 hi/lo split, V as tf32-rounded fp32.
// ---------------------------------------------------------------------------
__global__ void qkv_kernel(const float* __restrict__ x,
                           const float* __restrict__ wt,
                           const float* __restrict__ wp,
                           const float* __restrict__ wg) {
    __shared__ float As[16][68];   // [k][m]
    __shared__ float Bs[16][64];   // [k][n]
    const int b  = blockIdx.z;
    const int n0 = blockIdx.x * 64;
    const int r0 = blockIdx.y * 64;

    const float* W;
    int mode;                       // 0=Q 1=K 2=V
    if (r0 < 128)      { W = wt; mode = 0; }
    else if (r0 < 256) { W = wp; mode = 1; }
    else               { W = wg; mode = 2; }
    const int rl0 = r0 & 127;

    const float* xb = x + (size_t)b * Cdim * Nn;

    const int tid = threadIdx.x;
    const int tx = tid & 15, ty = tid >> 4;

    float acc[4][4] = {};
    for (int k0 = 0; k0 < Cdim; k0 += 16) {
        #pragma unroll
        for (int i = 0; i < 4; i++) {
            int f = tid + i * 256;
            int m = f >> 4, k = f & 15;
            As[k][m] = W[(rl0 + m) * Cdim + k0 + k];
        }
        #pragma unroll
        for (int i = 0; i < 4; i++) {
            int f = tid + i * 256;
            int k = f >> 6, n = f & 63;
            Bs[k][n] = xb[(size_t)(k0 + k) * Nn + n0 + n];
        }
        __syncthreads();
        #pragma unroll
        for (int k = 0; k < 16; k++) {
            float4 a4 = *(const float4*)&As[k][ty * 4];
            float4 b4 = *(const float4*)&Bs[k][tx * 4];
            float a[4] = {a4.x, a4.y, a4.z, a4.w};
            float bv[4] = {b4.x, b4.y, b4.z, b4.w};
            #pragma unroll
            for (int i = 0; i < 4; i++)
                #pragma unroll
                for (int j = 0; j < 4; j++)
                    acc[i][j] = fmaf(a[i], bv[j], acc[i][j]);
        }
        __syncthreads();
    }

    #pragma unroll
    for (int j = 0; j < 4; j++) {
        const int n = n0 + tx * 4 + j;
        const size_t base = ((size_t)b * Nn + n) * Ddim + rl0 + ty * 4;
        if (mode == 2) {
            float4 vv;
            vv.x = __uint_as_float(f2tf(acc[0][j]));
            vv.y = __uint_as_float(f2tf(acc[1][j]));
            vv.z = __uint_as_float(f2tf(acc[2][j]));
            vv.w = __uint_as_float(f2tf(acc[3][j]));
            *(float4*)&g_V[base] = vv;
        } else {
            __nv_bfloat16* Hh = (mode == 0) ? g_Qh : g_Kh;
            __nv_bfloat16* Hl = (mode == 0) ? g_Ql : g_Kl;
            __nv_bfloat162 h01, h23, l01, l23;
            h01.x = __float2bfloat16_rn(acc[0][j]);
            h01.y = __float2bfloat16_rn(acc[1][j]);
            h23.x = __float2bfloat16_rn(acc[2][j]);
            h23.y = __float2bfloat16_rn(acc[3][j]);
            l01.x = __float2bfloat16_rn(acc[0][j] - __bfloat162float(h01.x));
            l01.y = __float2bfloat16_rn(acc[1][j] - __bfloat162float(h01.y));
            l23.x = __float2bfloat16_rn(acc[2][j] - __bfloat162float(h23.x));
            l23.y = __float2bfloat16_rn(acc[3][j] - __bfloat162float(h23.y));
            *(__nv_bfloat162*)&Hh[base]     = h01;
            *(__nv_bfloat162*)&Hh[base + 2] = h23;
            *(__nv_bfloat162*)&Hl[base]     = l01;
            *(__nv_bfloat162*)&Hl[base + 2] = l23;
        }
    }
}

// ---------------------------------------------------------------------------
// Kernel 2: flash attention. S = QK^T via bf16 hi/lo split on m16n8k16
// (3 MMAs per k16, fp32 accumulate, lo*lo dropped => score err ~4e-5).
// P*V via tf32 m16n8k8 (P,V pre-rounded to tf32).
// Block: 128 queries, 8 warps; key tile 64.
// SMEM word strides: Qh/Ql/Kh/Kl = 68 (bf16 rows of 136), Vs = 136, Ps = 68.
// ---------------------------------------------------------------------------
#define QW 68
#define VW 136
#define PW 68
#define SM_QH 0
#define SM_QL (128 * QW)
#define SM_KH (SM_QL + 128 * QW)
#define SM_KL (SM_KH + 64 * QW)
#define SM_VS (SM_KL + 64 * QW)
#define SM_PS (SM_VS + 64 * VW)
#define ATTN_WORDS (SM_PS + 128 * PW)
#define ATTN_SMEM (ATTN_WORDS * 4)

__device__ __forceinline__ void mma8(float* c, const uint32_t* a, const uint32_t* b) {
    asm volatile(
        "mma.sync.aligned.m16n8k8.row.col.f32.tf32.tf32.f32 "
        "{%0,%1,%2,%3},{%4,%5,%6,%7},{%8,%9},{%0,%1,%2,%3};"
        : "+f"(c[0]), "+f"(c[1]), "+f"(c[2]), "+f"(c[3])
        : "r"(a[0]), "r"(a[1]), "r"(a[2]), "r"(a[3]), "r"(b[0]), "r"(b[1]));
}

__device__ __forceinline__ void mma16(float* c, const uint32_t* a, const uint32_t* b) {
    asm volatile(
        "mma.sync.aligned.m16n8k16.row.col.f32.bf16.bf16.f32 "
        "{%0,%1,%2,%3},{%4,%5,%6,%7},{%8,%9},{%0,%1,%2,%3};"
        : "+f"(c[0]), "+f"(c[1]), "+f"(c[2]), "+f"(c[3])
        : "r"(a[0]), "r"(a[1]), "r"(a[2]), "r"(a[3]), "r"(b[0]), "r"(b[1]));
}

__global__ void __launch_bounds__(256, 1) attn_kernel() {
    extern __shared__ float sm[];
    uint32_t* Qh = (uint32_t*)sm + SM_QH;   // [128][64 w] stride QW
    uint32_t* Ql = (uint32_t*)sm + SM_QL;
    uint32_t* Kh = (uint32_t*)sm + SM_KH;   // [64][64 w] stride QW
    uint32_t* Kl = (uint32_t*)sm + SM_KL;
    float*    Vs = sm + SM_VS;              // [64][128] stride VW
    float*    Ps = sm + SM_PS;              // [128][64] stride PW

    const int b  = blockIdx.y;
    const int q0 = blockIdx.x * 128;
    const uint32_t* Qgh = (const uint32_t*)(g_Qh + ((size_t)b * Nn + q0) * Ddim);
    const uint32_t* Qgl = (const uint32_t*)(g_Ql + ((size_t)b * Nn + q0) * Ddim);
    const uint32_t* Kgh = (const uint32_t*)(g_Kh + (size_t)b * Nn * Ddim);
    const uint32_t* Kgl = (const uint32_t*)(g_Kl + (size_t)b * Nn * Ddim);
    const float*    Vg  = g_V + (size_t)b * Nn * Ddim;
    float*          Yg  = g_Y + (size_t)b * Nn * Ddim;

    const int tid  = threadIdx.x;
    const int lane = tid & 31;
    const int w    = tid >> 5;
    const int g    = lane >> 2;
    const int t    = lane & 3;

    // Load Q hi/lo (bf16, 64 words per row)
    #pragma unroll
    for (int i = 0; i < 8; i++) {
        int f = tid + i * 256;           // 0..2047 uint4
        int r = f >> 4, cw = (f & 15) * 4;
        *(uint4*)&Qh[r * QW + cw] = *(const uint4*)&Qgh[r * 64 + cw];
        *(uint4*)&Ql[r * QW + cw] = *(const uint4*)&Qgl[r * 64 + cw];
    }

    float m0 = -1e30f, m1 = -1e30f, l0 = 0.f, l1 = 0.f;
    float o[16][4];
    #pragma unroll
    for (int nb = 0; nb < 16; nb++)
        #pragma unroll
        for (int c = 0; c < 4; c++) o[nb][c] = 0.f;

    const int row0 = w * 16 + g;
    const int row1 = row0 + 8;

    for (int j0 = 0; j0 < Nn; j0 += 64) {
        __syncthreads();
        // K tiles (bf16 hi/lo) + V tile (fp32, pre-rounded tf32)
        #pragma unroll
        for (int i = 0; i < 4; i++) {
            int f = tid + i * 256;       // 0..1023 uint4
            int r = f >> 4, cw = (f & 15) * 4;
            *(uint4*)&Kh[r * QW + cw] = *(const uint4*)&Kgh[(size_t)(j0 + r) * 64 + cw];
            *(uint4*)&Kl[r * QW + cw] = *(const uint4*)&Kgl[(size_t)(j0 + r) * 64 + cw];
        }
        #pragma unroll
        for (int i = 0; i < 8; i++) {
            int f = tid + i * 256;       // 0..2047 uint4
            int r = f >> 5, c4 = (f & 31) * 4;
            *(float4*)&Vs[r * VW + c4] = *(const float4*)&Vg[(size_t)(j0 + r) * Ddim + c4];
        }
        __syncthreads();

        // ---- S = Q K^T : bf16 split (qh*kh + qh*kl + ql*kh) ----
        float s[8][4];
        #pragma unroll
        for (int nb = 0; nb < 8; nb++)
            #pragma unroll
            for (int c = 0; c < 4; c++) s[nb][c] = 0.f;

        #pragma unroll
        for (int kb = 0; kb < 8; kb++) {
            const int kw = kb * 8 + t;
            uint32_t ah[4], al[4];
            ah[0] = Qh[row0 * QW + kw];
            ah[1] = Qh[row1 * QW + kw];
            ah[2] = Qh[row0 * QW + kw + 4];
            ah[3] = Qh[row1 * QW + kw + 4];
            al[0] = Ql[row0 * QW + kw];
            al[1] = Ql[row1 * QW + kw];
            al[2] = Ql[row0 * QW + kw + 4];
            al[3] = Ql[row1 * QW + kw + 4];
            #pragma unroll
            for (int nb = 0; nb < 8; nb++) {
                const int key = nb * 8 + g;
                uint32_t bh[2], bl[2];
                bh[0] = Kh[key * QW + kw];
                bh[1] = Kh[key * QW + kw + 4];
                bl[0] = Kl[key * QW + kw];
                bl[1] = Kl[key * QW + kw + 4];
                mma16(s[nb], ah, bh);
                mma16(s[nb], ah, bl);
                mma16(s[nb], al, bh);
            }
        }

        // ---- online softmax ----
        float mx0 = -1e30f, mx1 = -1e30f;
        #pragma unroll
        for (int nb = 0; nb < 8; nb++) {
            mx0 = fmaxf(mx0, fmaxf(s[nb][0], s[nb][1]));
            mx1 = fmaxf(mx1, fmaxf(s[nb][2], s[nb][3]));
        }
        mx0 = fmaxf(mx0, __shfl_xor_sync(0xffffffffu, mx0, 1));
        mx0 = fmaxf(mx0, __shfl_xor_sync(0xffffffffu, mx0, 2));
        mx1 = fmaxf(mx1, __shfl_xor_sync(0xffffffffu, mx1, 1));
        mx1 = fmaxf(mx1, __shfl_xor_sync(0xffffffffu, mx1, 2));
        float mn0 = fmaxf(m0, mx0), mn1 = fmaxf(m1, mx1);
        float sc0 = __expf(m0 - mn0), sc1 = __expf(m1 - mn1);
        m0 = mn0; m1 = mn1;
        l0 *= sc0; l1 *= sc1;
        #pragma unroll
        for (int nb = 0; nb < 16; nb++) {
            o[nb][0] *= sc0; o[nb][1] *= sc0;
            o[nb][2] *= sc1; o[nb][3] *= sc1;
        }
        float rs0 = 0.f, rs1 = 0.f;
        #pragma unroll
        for (int nb = 0; nb < 8; nb++) {
            float p0 = __expf(s[nb][0] - mn0);
            float p1 = __expf(s[nb][1] - mn0);
            float p2 = __expf(s[nb][2] - mn1);
            float p3 = __expf(s[nb][3] - mn1);
            rs0 += p0 + p1;
            rs1 += p2 + p3;
            float2 hi = make_float2(__uint_as_float(f2tf(p0)), __uint_as_float(f2tf(p1)));
            float2 lo = make_float2(__uint_as_float(f2tf(p2)), __uint_as_float(f2tf(p3)));
            *(float2*)&Ps[row0 * PW + nb * 8 + t * 2] = hi;
            *(float2*)&Ps[row1 * PW + nb * 8 + t * 2] = lo;
        }
        rs0 += __shfl_xor_sync(0xffffffffu, rs0, 1);
        rs0 += __shfl_xor_sync(0xffffffffu, rs0, 2);
        rs1 += __shfl_xor_sync(0xffffffffu, rs1, 1);
        rs1 += __shfl_xor_sync(0xffffffffu, rs1, 2);
        l0 += rs0; l1 += rs1;
        __syncwarp();  // P rows are warp-private: order STS -> LDS within warp

        // ---- O += P V (tf32) ----
        #pragma unroll
        for (int kb = 0; kb < 8; kb++) {
            const int kc = kb * 8 + t;
            uint32_t pa[4];
            pa[0] = __float_as_uint(Ps[row0 * PW + kc]);
            pa[1] = __float_as_uint(Ps[row1 * PW + kc]);
            pa[2] = __float_as_uint(Ps[row0 * PW + kc + 4]);
            pa[3] = __float_as_uint(Ps[row1 * PW + kc + 4]);
            #pragma unroll
            for (int nb = 0; nb < 16; nb++) {
                uint32_t vb[2];
                vb[0] = __float_as_uint(Vs[(kb * 8 + t) * VW + nb * 8 + g]);
                vb[1] = __float_as_uint(Vs[(kb * 8 + t + 4) * VW + nb * 8 + g]);
                mma8(o[nb], pa, vb);
            }
        }
    }

    // Normalize and write y[b][n][d]
    float inv0 = 1.f / l0, inv1 = 1.f / l1;
    #pragma unroll
    for (int nb = 0; nb < 16; nb++) {
        size_t r0o = (size_t)(q0 + row0) * Ddim + nb * 8 + t * 2;
        size_t r1o = (size_t)(q0 + row1) * Ddim + nb * 8 + t * 2;
        *(float2*)&Yg[r0o] = make_float2(o[nb][0] * inv0, o[nb][1] * inv0);
        *(float2*)&Yg[r1o] = make_float2(o[nb][2] * inv1, o[nb][3] * inv1);
    }
}

// ---------------------------------------------------------------------------
// Kernel 3: out = x + w_out * y. Both tiles transposed to [k][m] for LDS.128.
// ---------------------------------------------------------------------------
__global__ void out_kernel(const float* __restrict__ x,
                           const float* __restrict__ wo,
                           float* __restrict__ out) {
    __shared__ float As[16][68];   // w_out [k][c]
    __shared__ float Bs[16][68];   // y     [k][n]
    const int b  = blockIdx.z;
    const int n0 = blockIdx.x * 64;
    const int c0 = blockIdx.y * 64;
    const float* Yb = g_Y + (size_t)b * Nn * Ddim;
    const int tid = threadIdx.x;
    const int tx = tid & 15, ty = tid >> 4;

    float acc[4][4] = {};
    for (int k0 = 0; k0 < Ddim; k0 += 16) {
        #pragma unroll
        for (int i = 0; i < 4; i++) {
            int f = tid + i * 256;
            int m = f >> 4, k = f & 15;
            As[k][m] = wo[(c0 + m) * Ddim + k0 + k];
            Bs[k][m] = Yb[(size_t)(n0 + m) * Ddim + k0 + k];
        }
        __syncthreads();
        #pragma unroll
        for (int k = 0; k < 16; k++) {
            float4 a4 = *(const float4*)&As[k][ty * 4];
            float4 b4 = *(const float4*)&Bs[k][tx * 4];
            float a[4] = {a4.x, a4.y, a4.z, a4.w};
            float bv[4] = {b4.x, b4.y, b4.z, b4.w};
            #pragma unroll
            for (int i = 0; i < 4; i++)
                #pragma unroll
                for (int j = 0; j < 4; j++)
                    acc[i][j] = fmaf(a[i], bv[j], acc[i][j]);
        }
        __syncthreads();
    }
    #pragma unroll
    for (int i = 0; i < 4; i++)
        #pragma unroll
        for (int j = 0; j < 4; j++) {
            size_t idx = (size_t)b * Cdim * Nn +
                         (size_t)(c0 + ty * 4 + i) * Nn + n0 + tx * 4 + j;
            out[idx] = x[idx] + acc[i][j];
        }
}

// ---------------------------------------------------------------------------
extern "C" void kernel_launch(void* const* d_in, const int* in_sizes, int n_in,
                              void* d_out, int out_size) {
    const float* x  = (const float*)d_in[0];
    const float* wt = (const float*)d_in[1];
    const float* wp = (const float*)d_in[2];
    const float* wg = (const float*)d_in[3];
    const float* wo = (const float*)d_in[4];
    float* out = (float*)d_out;

    cudaFuncSetAttribute(attn_kernel,
                         cudaFuncAttributeMaxDynamicSharedMemorySize, ATTN_SMEM);

    qkv_kernel<<<dim3(Nn / 64, 6, Bsz), 256>>>(x, wt, wp, wg);
    attn_kernel<<<dim3(Nn / 128, Bsz), 256, ATTN_SMEM>>>();
    out_kernel<<<dim3(Nn / 64, Cdim / 64, Bsz), 256>>>(x, wo, out);
}

// round 6
// speedup vs baseline: 3.7575x; 1.1634x over previous
#include <cuda_runtime.h>
#include <cuda_bf16.h>
#include <cstdint>
#include <math.h>

#define Bsz  4
#define Cdim 256
#define Ddim 128
#define Nn   4096

// Scratch (static __device__ — no allocations allowed)
__device__ __nv_bfloat16 g_Qh[Bsz * Nn * Ddim];
__device__ __nv_bfloat16 g_Ql[Bsz * Nn * Ddim];
__device__ __nv_bfloat16 g_Kh[Bsz * Nn * Ddim];
__device__ __nv_bfloat16 g_Kl[Bsz * Nn * Ddim];
__device__ float g_V[Bsz * Nn * Ddim];                 // tf32-pre-rounded
__device__ __nv_bfloat16 g_Yh[Bsz * Nn * Ddim];
__device__ __nv_bfloat16 g_Yl[Bsz * Nn * Ddim];
__device__ __nv_bfloat16 g_Xth[Bsz * Nn * Cdim];       // x^T split
__device__ __nv_bfloat16 g_Xtl[Bsz * Nn * Cdim];
__device__ __nv_bfloat16 g_Wh[4 * 32768];              // wt,wp,wg,w_out split
__device__ __nv_bfloat16 g_Wl[4 * 32768];

__device__ __forceinline__ uint32_t f2tf(float x) {
    uint32_t r;
    asm("cvt.rna.tf32.f32 %0, %1;" : "=r"(r) : "f"(x));
    return r;
}

__device__ __forceinline__ void mma8(float* c, const uint32_t* a, const uint32_t* b) {
    asm volatile(
        "mma.sync.aligned.m16n8k8.row.col.f32.tf32.tf32.f32 "
        "{%0,%1,%2,%3},{%4,%5,%6,%7},{%8,%9},{%0,%1,%2,%3};"
        : "+f"(c[0]), "+f"(c[1]), "+f"(c[2]), "+f"(c[3])
        : "r"(a[0]), "r"(a[1]), "r"(a[2]), "r"(a[3]), "r"(b[0]), "r"(b[1]));
}

__device__ __forceinline__ void mma16(float* c, const uint32_t* a, const uint32_t* b) {
    asm volatile(
        "mma.sync.aligned.m16n8k16.row.col.f32.bf16.bf16.f32 "
        "{%0,%1,%2,%3},{%4,%5,%6,%7},{%8,%9},{%0,%1,%2,%3};"
        : "+f"(c[0]), "+f"(c[1]), "+f"(c[2]), "+f"(c[3])
        : "r"(a[0]), "r"(a[1]), "r"(a[2]), "r"(a[3]), "r"(b[0]), "r"(b[1]));
}

// ---------------------------------------------------------------------------
// Prep 1: split a 32768-element fp32 weight into bf16 hi/lo at slot.
// ---------------------------------------------------------------------------
__global__ void split_w_kernel(const float* __restrict__ src, int slot) {
    int i = blockIdx.x * 256 + threadIdx.x;
    float v = src[i];
    __nv_bfloat16 h = __float2bfloat16_rn(v);
    __nv_bfloat16 l = __float2bfloat16_rn(v - __bfloat162float(h));
    g_Wh[slot * 32768 + i] = h;
    g_Wl[slot * 32768 + i] = l;
}

// ---------------------------------------------------------------------------
// Prep 2: transpose-split x[b][c][n] -> xt[b][n][c] bf16 hi/lo.
// ---------------------------------------------------------------------------
__global__ void xpose_kernel(const float* __restrict__ x) {
    __shared__ float tsm[32][33];
    const int b = blockIdx.z, n0 = blockIdx.x * 32, c0 = blockIdx.y * 32;
    const int tx = threadIdx.x & 31, ty = threadIdx.x >> 5;
    const float* xb = x + (size_t)b * Cdim * Nn;
    #pragma unroll
    for (int i = 0; i < 4; i++)
        tsm[ty + 8 * i][tx] = xb[(size_t)(c0 + ty + 8 * i) * Nn + n0 + tx];
    __syncthreads();
    #pragma unroll
    for (int i = 0; i < 4; i++) {
        float v = tsm[tx][ty + 8 * i];
        __nv_bfloat16 h = __float2bfloat16_rn(v);
        __nv_bfloat16 l = __float2bfloat16_rn(v - __bfloat162float(h));
        size_t o = ((size_t)b * Nn + n0 + ty + 8 * i) * Cdim + c0 + tx;
        g_Xth[o] = h;
        g_Xtl[o] = l;
    }
}

// ---------------------------------------------------------------------------
// Kernel 1: QKV projection on tensor cores (bf16 hi/lo split, 3 MMAs).
// Block: (128 pixels) x (128 outputs = full d), K=256 in 4 chunks of 64.
// A = x^T [pixel][c] (from g_Xt*), B = W [r][c] (from g_W*).
// Epilogue: slot 0/1 -> Q/K bf16 hi/lo split; slot 2 -> V tf32-rounded f32.
// SMEM stride 36 words per 32-word row => conflict-free frag loads.
// ---------------------------------------------------------------------------
#define P36 36
#define QKV_XH 0
#define QKV_XL (128 * P36)
#define QKV_WH (2 * 128 * P36)
#define QKV_WL (3 * 128 * P36)
#define QKV_SMEM (4 * 128 * P36 * 4)

__global__ void __launch_bounds__(256, 1) qkv_tc_kernel() {
    extern __shared__ uint32_t S[];
    const int b = blockIdx.z, slot = blockIdx.y, n0 = blockIdx.x * 128;
    const int tid = threadIdx.x;
    const int lane = tid & 31, w = tid >> 5;
    const int g = lane >> 2, t = lane & 3;
    const int row0 = w * 16 + g, row1 = row0 + 8;

    const uint32_t* Xhw = (const uint32_t*)g_Xth;
    const uint32_t* Xlw = (const uint32_t*)g_Xtl;
    const uint32_t* Whw = (const uint32_t*)(g_Wh + slot * 32768);
    const uint32_t* Wlw = (const uint32_t*)(g_Wl + slot * 32768);

    float acc[16][4];
    #pragma unroll
    for (int nb = 0; nb < 16; nb++)
        #pragma unroll
        for (int c = 0; c < 4; c++) acc[nb][c] = 0.f;

    for (int chunk = 0; chunk < 4; chunk++) {
        const int c0 = chunk * 64;
        __syncthreads();
        // Stage X (128 rows x 32 words) and W (128 rows x 32 words), hi+lo
        #pragma unroll
        for (int i = 0; i < 4; i++) {
            int f = tid + i * 256;            // 0..1023
            int r = f >> 3, w4 = (f & 7) * 4;
            size_t xb = ((size_t)(b * Nn + n0 + r) * Cdim + c0) >> 1;
            *(uint4*)&S[QKV_XH + r * P36 + w4] = *(const uint4*)&Xhw[xb + w4];
            *(uint4*)&S[QKV_XL + r * P36 + w4] = *(const uint4*)&Xlw[xb + w4];
            int wb = r * 128 + (c0 >> 1);
            *(uint4*)&S[QKV_WH + r * P36 + w4] = *(const uint4*)&Whw[wb + w4];
            *(uint4*)&S[QKV_WL + r * P36 + w4] = *(const uint4*)&Wlw[wb + w4];
        }
        __syncthreads();

        #pragma unroll
        for (int kb = 0; kb < 4; kb++) {
            const int kw = kb * 8 + t;
            uint32_t ah[4], al[4];
            ah[0] = S[QKV_XH + row0 * P36 + kw];
            ah[1] = S[QKV_XH + row1 * P36 + kw];
            ah[2] = S[QKV_XH + row0 * P36 + kw + 4];
            ah[3] = S[QKV_XH + row1 * P36 + kw + 4];
            al[0] = S[QKV_XL + row0 * P36 + kw];
            al[1] = S[QKV_XL + row1 * P36 + kw];
            al[2] = S[QKV_XL + row0 * P36 + kw + 4];
            al[3] = S[QKV_XL + row1 * P36 + kw + 4];
            #pragma unroll
            for (int nb = 0; nb < 16; nb++) {
                const int rr = nb * 8 + g;
                uint32_t bh[2], bl[2];
                bh[0] = S[QKV_WH + rr * P36 + kw];
                bh[1] = S[QKV_WH + rr * P36 + kw + 4];
                bl[0] = S[QKV_WL + rr * P36 + kw];
                bl[1] = S[QKV_WL + rr * P36 + kw + 4];
                mma16(acc[nb], ah, bh);
                mma16(acc[nb], ah, bl);
                mma16(acc[nb], al, bh);
            }
        }
    }

    // Epilogue
    const size_t base0 = ((size_t)b * Nn + n0 + row0) * Ddim;
    const size_t base1 = ((size_t)b * Nn + n0 + row1) * Ddim;
    if (slot == 2) {
        #pragma unroll
        for (int nb = 0; nb < 16; nb++) {
            const int d = nb * 8 + t * 2;
            *(float2*)&g_V[base0 + d] = make_float2(
                __uint_as_float(f2tf(acc[nb][0])), __uint_as_float(f2tf(acc[nb][1])));
            *(float2*)&g_V[base1 + d] = make_float2(
                __uint_as_float(f2tf(acc[nb][2])), __uint_as_float(f2tf(acc[nb][3])));
        }
    } else {
        __nv_bfloat16* Hh = (slot == 0) ? g_Qh : g_Kh;
        __nv_bfloat16* Hl = (slot == 0) ? g_Ql : g_Kl;
        #pragma unroll
        for (int nb = 0; nb < 16; nb++) {
            const int d = nb * 8 + t * 2;
            __nv_bfloat162 h0, l0, h1, l1;
            h0.x = __float2bfloat16_rn(acc[nb][0]);
            h0.y = __float2bfloat16_rn(acc[nb][1]);
            l0.x = __float2bfloat16_rn(acc[nb][0] - __bfloat162float(h0.x));
            l0.y = __float2bfloat16_rn(acc[nb][1] - __bfloat162float(h0.y));
            h1.x = __float2bfloat16_rn(acc[nb][2]);
            h1.y = __float2bfloat16_rn(acc[nb][3]);
            l1.x = __float2bfloat16_rn(acc[nb][2] - __bfloat162float(h1.x));
            l1.y = __float2bfloat16_rn(acc[nb][3] - __bfloat162float(h1.y));
            *(__nv_bfloat162*)&Hh[base0 + d] = h0;
            *(__nv_bfloat162*)&Hl[base0 + d] = l0;
            *(__nv_bfloat162*)&Hh[base1 + d] = h1;
            *(__nv_bfloat162*)&Hl[base1 + d] = l1;
        }
    }
}

// ---------------------------------------------------------------------------
// Kernel 2: flash attention (R4 mainloop; epilogue emits Y bf16 hi/lo).
// ---------------------------------------------------------------------------
#define QW 68
#define VW 136
#define PW 68
#define SM_QH 0
#define SM_QL (128 * QW)
#define SM_KH (SM_QL + 128 * QW)
#define SM_KL (SM_KH + 64 * QW)
#define SM_VS (SM_KL + 64 * QW)
#define SM_PS (SM_VS + 64 * VW)
#define ATTN_WORDS (SM_PS + 128 * PW)
#define ATTN_SMEM (ATTN_WORDS * 4)

__global__ void __launch_bounds__(256, 1) attn_kernel() {
    extern __shared__ float sm[];
    uint32_t* Qh = (uint32_t*)sm + SM_QH;
    uint32_t* Ql = (uint32_t*)sm + SM_QL;
    uint32_t* Kh = (uint32_t*)sm + SM_KH;
    uint32_t* Kl = (uint32_t*)sm + SM_KL;
    float*    Vs = sm + SM_VS;
    float*    Ps = sm + SM_PS;

    const int b  = blockIdx.y;
    const int q0 = blockIdx.x * 128;
    const uint32_t* Qgh = (const uint32_t*)(g_Qh + ((size_t)b * Nn + q0) * Ddim);
    const uint32_t* Qgl = (const uint32_t*)(g_Ql + ((size_t)b * Nn + q0) * Ddim);
    const uint32_t* Kgh = (const uint32_t*)(g_Kh + (size_t)b * Nn * Ddim);
    const uint32_t* Kgl = (const uint32_t*)(g_Kl + (size_t)b * Nn * Ddim);
    const float*    Vg  = g_V + (size_t)b * Nn * Ddim;

    const int tid  = threadIdx.x;
    const int lane = tid & 31;
    const int w    = tid >> 5;
    const int g    = lane >> 2;
    const int t    = lane & 3;

    #pragma unroll
    for (int i = 0; i < 8; i++) {
        int f = tid + i * 256;
        int r = f >> 4, cw = (f & 15) * 4;
        *(uint4*)&Qh[r * QW + cw] = *(const uint4*)&Qgh[r * 64 + cw];
        *(uint4*)&Ql[r * QW + cw] = *(const uint4*)&Qgl[r * 64 + cw];
    }

    float m0 = -1e30f, m1 = -1e30f, l0 = 0.f, l1 = 0.f;
    float o[16][4];
    #pragma unroll
    for (int nb = 0; nb < 16; nb++)
        #pragma unroll
        for (int c = 0; c < 4; c++) o[nb][c] = 0.f;

    const int row0 = w * 16 + g;
    const int row1 = row0 + 8;

    for (int j0 = 0; j0 < Nn; j0 += 64) {
        __syncthreads();
        #pragma unroll
        for (int i = 0; i < 4; i++) {
            int f = tid + i * 256;
            int r = f >> 4, cw = (f & 15) * 4;
            *(uint4*)&Kh[r * QW + cw] = *(const uint4*)&Kgh[(size_t)(j0 + r) * 64 + cw];
            *(uint4*)&Kl[r * QW + cw] = *(const uint4*)&Kgl[(size_t)(j0 + r) * 64 + cw];
        }
        #pragma unroll
        for (int i = 0; i < 8; i++) {
            int f = tid + i * 256;
            int r = f >> 5, c4 = (f & 31) * 4;
            *(float4*)&Vs[r * VW + c4] = *(const float4*)&Vg[(size_t)(j0 + r) * Ddim + c4];
        }
        __syncthreads();

        float s[8][4];
        #pragma unroll
        for (int nb = 0; nb < 8; nb++)
            #pragma unroll
            for (int c = 0; c < 4; c++) s[nb][c] = 0.f;

        #pragma unroll
        for (int kb = 0; kb < 8; kb++) {
            const int kw = kb * 8 + t;
            uint32_t ah[4], al[4];
            ah[0] = Qh[row0 * QW + kw];
            ah[1] = Qh[row1 * QW + kw];
            ah[2] = Qh[row0 * QW + kw + 4];
            ah[3] = Qh[row1 * QW + kw + 4];
            al[0] = Ql[row0 * QW + kw];
            al[1] = Ql[row1 * QW + kw];
            al[2] = Ql[row0 * QW + kw + 4];
            al[3] = Ql[row1 * QW + kw + 4];
            #pragma unroll
            for (int nb = 0; nb < 8; nb++) {
                const int key = nb * 8 + g;
                uint32_t bh[2], bl[2];
                bh[0] = Kh[key * QW + kw];
                bh[1] = Kh[key * QW + kw + 4];
                bl[0] = Kl[key * QW + kw];
                bl[1] = Kl[key * QW + kw + 4];
                mma16(s[nb], ah, bh);
                mma16(s[nb], ah, bl);
                mma16(s[nb], al, bh);
            }
        }

        float mx0 = -1e30f, mx1 = -1e30f;
        #pragma unroll
        for (int nb = 0; nb < 8; nb++) {
            mx0 = fmaxf(mx0, fmaxf(s[nb][0], s[nb][1]));
            mx1 = fmaxf(mx1, fmaxf(s[nb][2], s[nb][3]));
        }
        mx0 = fmaxf(mx0, __shfl_xor_sync(0xffffffffu, mx0, 1));
        mx0 = fmaxf(mx0, __shfl_xor_sync(0xffffffffu, mx0, 2));
        mx1 = fmaxf(mx1, __shfl_xor_sync(0xffffffffu, mx1, 1));
        mx1 = fmaxf(mx1, __shfl_xor_sync(0xffffffffu, mx1, 2));
        float mn0 = fmaxf(m0, mx0), mn1 = fmaxf(m1, mx1);
        float sc0 = __expf(m0 - mn0), sc1 = __expf(m1 - mn1);
        m0 = mn0; m1 = mn1;
        l0 *= sc0; l1 *= sc1;
        #pragma unroll
        for (int nb = 0; nb < 16; nb++) {
            o[nb][0] *= sc0; o[nb][1] *= sc0;
            o[nb][2] *= sc1; o[nb][3] *= sc1;
        }
        float rs0 = 0.f, rs1 = 0.f;
        #pragma unroll
        for (int nb = 0; nb < 8; nb++) {
            float p0 = __expf(s[nb][0] - mn0);
            float p1 = __expf(s[nb][1] - mn0);
            float p2 = __expf(s[nb][2] - mn1);
            float p3 = __expf(s[nb][3] - mn1);
            rs0 += p0 + p1;
            rs1 += p2 + p3;
            float2 hi = make_float2(__uint_as_float(f2tf(p0)), __uint_as_float(f2tf(p1)));
            float2 lo = make_float2(__uint_as_float(f2tf(p2)), __uint_as_float(f2tf(p3)));
            *(float2*)&Ps[row0 * PW + nb * 8 + t * 2] = hi;
            *(float2*)&Ps[row1 * PW + nb * 8 + t * 2] = lo;
        }
        rs0 += __shfl_xor_sync(0xffffffffu, rs0, 1);
        rs0 += __shfl_xor_sync(0xffffffffu, rs0, 2);
        rs1 += __shfl_xor_sync(0xffffffffu, rs1, 1);
        rs1 += __shfl_xor_sync(0xffffffffu, rs1, 2);
        l0 += rs0; l1 += rs1;
        __syncwarp();

        #pragma unroll
        for (int kb = 0; kb < 8; kb++) {
            const int kc = kb * 8 + t;
            uint32_t pa[4];
            pa[0] = __float_as_uint(Ps[row0 * PW + kc]);
            pa[1] = __float_as_uint(Ps[row1 * PW + kc]);
            pa[2] = __float_as_uint(Ps[row0 * PW + kc + 4]);
            pa[3] = __float_as_uint(Ps[row1 * PW + kc + 4]);
            #pragma unroll
            for (int nb = 0; nb < 16; nb++) {
                uint32_t vb[2];
                vb[0] = __float_as_uint(Vs[(kb * 8 + t) * VW + nb * 8 + g]);
                vb[1] = __float_as_uint(Vs[(kb * 8 + t + 4) * VW + nb * 8 + g]);
                mma8(o[nb], pa, vb);
            }
        }
    }

    // Normalize and write Y as bf16 hi/lo split
    float inv0 = 1.f / l0, inv1 = 1.f / l1;
    const size_t base0 = ((size_t)b * Nn + q0 + row0) * Ddim;
    const size_t base1 = ((size_t)b * Nn + q0 + row1) * Ddim;
    #pragma unroll
    for (int nb = 0; nb < 16; nb++) {
        const int d = nb * 8 + t * 2;
        float y00 = o[nb][0] * inv0, y01 = o[nb][1] * inv0;
        float y10 = o[nb][2] * inv1, y11 = o[nb][3] * inv1;
        __nv_bfloat162 h0, l0v, h1, l1v;
        h0.x = __float2bfloat16_rn(y00);
        h0.y = __float2bfloat16_rn(y01);
        l0v.x = __float2bfloat16_rn(y00 - __bfloat162float(h0.x));
        l0v.y = __float2bfloat16_rn(y01 - __bfloat162float(h0.y));
        h1.x = __float2bfloat16_rn(y10);
        h1.y = __float2bfloat16_rn(y11);
        l1v.x = __float2bfloat16_rn(y10 - __bfloat162float(h1.x));
        l1v.y = __float2bfloat16_rn(y11 - __bfloat162float(h1.y));
        *(__nv_bfloat162*)&g_Yh[base0 + d] = h0;
        *(__nv_bfloat162*)&g_Yl[base0 + d] = l0v;
        *(__nv_bfloat162*)&g_Yh[base1 + d] = h1;
        *(__nv_bfloat162*)&g_Yl[base1 + d] = l1v;
    }
}

// ---------------------------------------------------------------------------
// Kernel 3: out = x + w_out * y on tensor cores (bf16 hi/lo split).
// Block: 128 channels x 64 pixels, K=128 in 2 chunks of 64.
// A = w_out [c][dd] (slot 3 of g_W*), B = Y [pixel][dd] (g_Y*).
// ---------------------------------------------------------------------------
#define OUT_AH 0
#define OUT_AL (128 * P36)
#define OUT_BH (2 * 128 * P36)
#define OUT_BL (2 * 128 * P36 + 64 * P36)
#define OUT_SMEM ((2 * 128 * P36 + 2 * 64 * P36) * 4)

__global__ void __launch_bounds__(256) out_tc_kernel(const float* __restrict__ x,
                                                     float* __restrict__ out) {
    extern __shared__ uint32_t S[];
    const int b = blockIdx.z, c0 = blockIdx.y * 128, n0 = blockIdx.x * 64;
    const int tid = threadIdx.x;
    const int lane = tid & 31, w = tid >> 5;
    const int g = lane >> 2, t = lane & 3;
    const int row0 = w * 16 + g, row1 = row0 + 8;

    const uint32_t* Ahw = (const uint32_t*)(g_Wh + 3 * 32768);
    const uint32_t* Alw = (const uint32_t*)(g_Wl + 3 * 32768);
    const uint32_t* Bhw = (const uint32_t*)g_Yh;
    const uint32_t* Blw = (const uint32_t*)g_Yl;

    float acc[8][4];
    #pragma unroll
    for (int nb = 0; nb < 8; nb++)
        #pragma unroll
        for (int c = 0; c < 4; c++) acc[nb][c] = 0.f;

    for (int chunk = 0; chunk < 2; chunk++) {
        const int dd0 = chunk * 64;
        __syncthreads();
        #pragma unroll
        for (int i = 0; i < 4; i++) {
            int f = tid + i * 256;            // 0..1023
            int r = f >> 3, w4 = (f & 7) * 4;
            int ab = (c0 + r) * 64 + (dd0 >> 1);
            *(uint4*)&S[OUT_AH + r * P36 + w4] = *(const uint4*)&Ahw[ab + w4];
            *(uint4*)&S[OUT_AL + r * P36 + w4] = *(const uint4*)&Alw[ab + w4];
        }
        #pragma unroll
        for (int i = 0; i < 2; i++) {
            int f = tid + i * 256;            // 0..511
            int r = f >> 3, w4 = (f & 7) * 4;
            size_t bb = ((size_t)(b * Nn + n0 + r) * Ddim + dd0) >> 1;
            *(uint4*)&S[OUT_BH + r * P36 + w4] = *(const uint4*)&Bhw[bb + w4];
            *(uint4*)&S[OUT_BL + r * P36 + w4] = *(const uint4*)&Blw[bb + w4];
        }
        __syncthreads();

        #pragma unroll
        for (int kb = 0; kb < 4; kb++) {
            const int kw = kb * 8 + t;
            uint32_t ah[4], al[4];
            ah[0] = S[OUT_AH + row0 * P36 + kw];
            ah[1] = S[OUT_AH + row1 * P36 + kw];
            ah[2] = S[OUT_AH + row0 * P36 + kw + 4];
            ah[3] = S[OUT_AH + row1 * P36 + kw + 4];
            al[0] = S[OUT_AL + row0 * P36 + kw];
            al[1] = S[OUT_AL + row1 * P36 + kw];
            al[2] = S[OUT_AL + row0 * P36 + kw + 4];
            al[3] = S[OUT_AL + row1 * P36 + kw + 4];
            #pragma unroll
            for (int nb = 0; nb < 8; nb++) {
                const int rr = nb * 8 + g;
                uint32_t bh[2], bl[2];
                bh[0] = S[OUT_BH + rr * P36 + kw];
                bh[1] = S[OUT_BH + rr * P36 + kw + 4];
                bl[0] = S[OUT_BL + rr * P36 + kw];
                bl[1] = S[OUT_BL + rr * P36 + kw + 4];
                mma16(acc[nb], ah, bh);
                mma16(acc[nb], ah, bl);
                mma16(acc[nb], al, bh);
            }
        }
    }

    // Epilogue: residual add, write out[b][c][n]
    const int ch0 = c0 + row0, ch1 = c0 + row1;
    #pragma unroll
    for (int nb = 0; nb < 8; nb++) {
        const int pix = n0 + nb * 8 + t * 2;
        size_t i0 = (size_t)b * Cdim * Nn + (size_t)ch0 * Nn + pix;
        size_t i1 = (size_t)b * Cdim * Nn + (size_t)ch1 * Nn + pix;
        float2 x0 = *(const float2*)&x[i0];
        float2 x1 = *(const float2*)&x[i1];
        *(float2*)&out[i0] = make_float2(x0.x + acc[nb][0], x0.y + acc[nb][1]);
        *(float2*)&out[i1] = make_float2(x1.x + acc[nb][2], x1.y + acc[nb][3]);
    }
}

// ---------------------------------------------------------------------------
extern "C" void kernel_launch(void* const* d_in, const int* in_sizes, int n_in,
                              void* d_out, int out_size) {
    const float* x  = (const float*)d_in[0];
    const float* wt = (const float*)d_in[1];
    const float* wp = (const float*)d_in[2];
    const float* wg = (const float*)d_in[3];
    const float* wo = (const float*)d_in[4];
    float* out = (float*)d_out;

    cudaFuncSetAttribute(attn_kernel,
                         cudaFuncAttributeMaxDynamicSharedMemorySize, ATTN_SMEM);
    cudaFuncSetAttribute(qkv_tc_kernel,
                         cudaFuncAttributeMaxDynamicSharedMemorySize, QKV_SMEM);
    cudaFuncSetAttribute(out_tc_kernel,
                         cudaFuncAttributeMaxDynamicSharedMemorySize, OUT_SMEM);

    split_w_kernel<<<128, 256>>>(wt, 0);
    split_w_kernel<<<128, 256>>>(wp, 1);
    split_w_kernel<<<128, 256>>>(wg, 2);
    split_w_kernel<<<128, 256>>>(wo, 3);
    xpose_kernel<<<dim3(Nn / 32, Cdim / 32, Bsz), 256>>>(x);
    qkv_tc_kernel<<<dim3(Nn / 128, 3, Bsz), 256, QKV_SMEM>>>();
    attn_kernel<<<dim3(Nn / 128, Bsz), 256, ATTN_SMEM>>>();
    out_tc_kernel<<<dim3(Nn / 64, Cdim / 128, Bsz), 256, OUT_SMEM>>>(x, out);
}

// round 8
// speedup vs baseline: 3.8529x; 1.0254x over previous
#include <cuda_runtime.h>
#include <cuda_bf16.h>
#include <cstdint>
#include <math.h>

#define Bsz  4
#define Cdim 256
#define Ddim 128
#define Nn   4096

// Scratch (static __device__ — no allocations allowed)
__device__ __nv_bfloat16 g_Qh[Bsz * Nn * Ddim];
__device__ __nv_bfloat16 g_Ql[Bsz * Nn * Ddim];
__device__ __nv_bfloat16 g_Kh[Bsz * Nn * Ddim];
__device__ __nv_bfloat16 g_Kl[Bsz * Nn * Ddim];
__device__ float g_V[Bsz * Nn * Ddim];                 // tf32-pre-rounded
__device__ __nv_bfloat16 g_Yh[Bsz * Nn * Ddim];
__device__ __nv_bfloat16 g_Yl[Bsz * Nn * Ddim];
__device__ __nv_bfloat16 g_Xth[Bsz * Nn * Cdim];       // x^T split
__device__ __nv_bfloat16 g_Xtl[Bsz * Nn * Cdim];
__device__ __nv_bfloat16 g_Wh[4 * 32768];              // wt,wp,wg,w_out split
__device__ __nv_bfloat16 g_Wl[4 * 32768];

__device__ __forceinline__ uint32_t f2tf(float x) {
    uint32_t r;
    asm("cvt.rna.tf32.f32 %0, %1;" : "=r"(r) : "f"(x));
    return r;
}

__device__ __forceinline__ void mma8(float* c, const uint32_t* a, const uint32_t* b) {
    asm volatile(
        "mma.sync.aligned.m16n8k8.row.col.f32.tf32.tf32.f32 "
        "{%0,%1,%2,%3},{%4,%5,%6,%7},{%8,%9},{%0,%1,%2,%3};"
        : "+f"(c[0]), "+f"(c[1]), "+f"(c[2]), "+f"(c[3])
        : "r"(a[0]), "r"(a[1]), "r"(a[2]), "r"(a[3]), "r"(b[0]), "r"(b[1]));
}

__device__ __forceinline__ void mma16(float* c, const uint32_t* a, const uint32_t* b) {
    asm volatile(
        "mma.sync.aligned.m16n8k16.row.col.f32.bf16.bf16.f32 "
        "{%0,%1,%2,%3},{%4,%5,%6,%7},{%8,%9},{%0,%1,%2,%3};"
        : "+f"(c[0]), "+f"(c[1]), "+f"(c[2]), "+f"(c[3])
        : "r"(a[0]), "r"(a[1]), "r"(a[2]), "r"(a[3]), "r"(b[0]), "r"(b[1]));
}

__device__ __forceinline__ void ldsm4(uint32_t* r, uint32_t addr) {
    asm volatile(
        "ldmatrix.sync.aligned.m8n8.x4.shared.b16 {%0,%1,%2,%3}, [%4];"
        : "=r"(r[0]), "=r"(r[1]), "=r"(r[2]), "=r"(r[3]) : "r"(addr));
}

__device__ __forceinline__ uint32_t smem_u32(const void* p) {
    uint32_t a;
    asm("{ .reg .u64 t; cvta.to.shared.u64 t, %1; cvt.u32.u64 %0, t; }" : "=r"(a) : "l"(p));
    return a;
}

// ---------------------------------------------------------------------------
// Prep 1: split all 4 fp32 weights into bf16 hi/lo (one launch).
// ---------------------------------------------------------------------------
__global__ void split_w4_kernel(const float* __restrict__ w0, const float* __restrict__ w1,
                                const float* __restrict__ w2, const float* __restrict__ w3) {
    int slot = blockIdx.y;
    const float* src = (slot == 0) ? w0 : (slot == 1) ? w1 : (slot == 2) ? w2 : w3;
    int i = blockIdx.x * 256 + threadIdx.x;
    float v = src[i];
    __nv_bfloat16 h = __float2bfloat16_rn(v);
    __nv_bfloat16 l = __float2bfloat16_rn(v - __bfloat162float(h));
    g_Wh[slot * 32768 + i] = h;
    g_Wl[slot * 32768 + i] = l;
}

// ---------------------------------------------------------------------------
// Prep 2: transpose-split x[b][c][n] -> xt[b][n][c] bf16 hi/lo.
// ---------------------------------------------------------------------------
__global__ void xpose_kernel(const float* __restrict__ x) {
    __shared__ float tsm[32][33];
    const int b = blockIdx.z, n0 = blockIdx.x * 32, c0 = blockIdx.y * 32;
    const int tx = threadIdx.x & 31, ty = threadIdx.x >> 5;
    const float* xb = x + (size_t)b * Cdim * Nn;
    #pragma unroll
    for (int i = 0; i < 4; i++)
        tsm[ty + 8 * i][tx] = xb[(size_t)(c0 + ty + 8 * i) * Nn + n0 + tx];
    __syncthreads();
    #pragma unroll
    for (int i = 0; i < 4; i++) {
        float v = tsm[tx][ty + 8 * i];
        __nv_bfloat16 h = __float2bfloat16_rn(v);
        __nv_bfloat16 l = __float2bfloat16_rn(v - __bfloat162float(h));
        size_t o = ((size_t)b * Nn + n0 + ty + 8 * i) * Cdim + c0 + tx;
        g_Xth[o] = h;
        g_Xtl[o] = l;
    }
}

// ---------------------------------------------------------------------------
// Kernel 1: QKV projection on tensor cores (unchanged from R6 pass).
// ---------------------------------------------------------------------------
#define P36 36
#define QKV_XH 0
#define QKV_XL (128 * P36)
#define QKV_WH (2 * 128 * P36)
#define QKV_WL (3 * 128 * P36)
#define QKV_SMEM (4 * 128 * P36 * 4)

__global__ void __launch_bounds__(256, 1) qkv_tc_kernel() {
    extern __shared__ uint32_t S[];
    const int b = blockIdx.z, slot = blockIdx.y, n0 = blockIdx.x * 128;
    const int tid = threadIdx.x;
    const int lane = tid & 31, w = tid >> 5;
    const int g = lane >> 2, t = lane & 3;
    const int row0 = w * 16 + g, row1 = row0 + 8;

    const uint32_t* Xhw = (const uint32_t*)g_Xth;
    const uint32_t* Xlw = (const uint32_t*)g_Xtl;
    const uint32_t* Whw = (const uint32_t*)(g_Wh + slot * 32768);
    const uint32_t* Wlw = (const uint32_t*)(g_Wl + slot * 32768);

    float acc[16][4];
    #pragma unroll
    for (int nb = 0; nb < 16; nb++)
        #pragma unroll
        for (int c = 0; c < 4; c++) acc[nb][c] = 0.f;

    for (int chunk = 0; chunk < 4; chunk++) {
        const int c0 = chunk * 64;
        __syncthreads();
        #pragma unroll
        for (int i = 0; i < 4; i++) {
            int f = tid + i * 256;
            int r = f >> 3, w4 = (f & 7) * 4;
            size_t xb = ((size_t)(b * Nn + n0 + r) * Cdim + c0) >> 1;
            *(uint4*)&S[QKV_XH + r * P36 + w4] = *(const uint4*)&Xhw[xb + w4];
            *(uint4*)&S[QKV_XL + r * P36 + w4] = *(const uint4*)&Xlw[xb + w4];
            int wb = r * 128 + (c0 >> 1);
            *(uint4*)&S[QKV_WH + r * P36 + w4] = *(const uint4*)&Whw[wb + w4];
            *(uint4*)&S[QKV_WL + r * P36 + w4] = *(const uint4*)&Wlw[wb + w4];
        }
        __syncthreads();

        #pragma unroll
        for (int kb = 0; kb < 4; kb++) {
            const int kw = kb * 8 + t;
            uint32_t ah[4], al[4];
            ah[0] = S[QKV_XH + row0 * P36 + kw];
            ah[1] = S[QKV_XH + row1 * P36 + kw];
            ah[2] = S[QKV_XH + row0 * P36 + kw + 4];
            ah[3] = S[QKV_XH + row1 * P36 + kw + 4];
            al[0] = S[QKV_XL + row0 * P36 + kw];
            al[1] = S[QKV_XL + row1 * P36 + kw];
            al[2] = S[QKV_XL + row0 * P36 + kw + 4];
            al[3] = S[QKV_XL + row1 * P36 + kw + 4];
            #pragma unroll
            for (int nb = 0; nb < 16; nb++) {
                const int rr = nb * 8 + g;
                uint32_t bh[2], bl[2];
                bh[0] = S[QKV_WH + rr * P36 + kw];
                bh[1] = S[QKV_WH + rr * P36 + kw + 4];
                bl[0] = S[QKV_WL + rr * P36 + kw];
                bl[1] = S[QKV_WL + rr * P36 + kw + 4];
                mma16(acc[nb], ah, bh);
                mma16(acc[nb], ah, bl);
                mma16(acc[nb], al, bh);
            }
        }
    }

    const size_t base0 = ((size_t)b * Nn + n0 + row0) * Ddim;
    const size_t base1 = ((size_t)b * Nn + n0 + row1) * Ddim;
    if (slot == 2) {
        #pragma unroll
        for (int nb = 0; nb < 16; nb++) {
            const int d = nb * 8 + t * 2;
            *(float2*)&g_V[base0 + d] = make_float2(
                __uint_as_float(f2tf(acc[nb][0])), __uint_as_float(f2tf(acc[nb][1])));
            *(float2*)&g_V[base1 + d] = make_float2(
                __uint_as_float(f2tf(acc[nb][2])), __uint_as_float(f2tf(acc[nb][3])));
        }
    } else {
        __nv_bfloat16* Hh = (slot == 0) ? g_Qh : g_Kh;
        __nv_bfloat16* Hl = (slot == 0) ? g_Ql : g_Kl;
        #pragma unroll
        for (int nb = 0; nb < 16; nb++) {
            const int d = nb * 8 + t * 2;
            __nv_bfloat162 h0, l0, h1, l1;
            h0.x = __float2bfloat16_rn(acc[nb][0]);
            h0.y = __float2bfloat16_rn(acc[nb][1]);
            l0.x = __float2bfloat16_rn(acc[nb][0] - __bfloat162float(h0.x));
            l0.y = __float2bfloat16_rn(acc[nb][1] - __bfloat162float(h0.y));
            h1.x = __float2bfloat16_rn(acc[nb][2]);
            h1.y = __float2bfloat16_rn(acc[nb][3]);
            l1.x = __float2bfloat16_rn(acc[nb][2] - __bfloat162float(h1.x));
            l1.y = __float2bfloat16_rn(acc[nb][3] - __bfloat162float(h1.y));
            *(__nv_bfloat162*)&Hh[base0 + d] = h0;
            *(__nv_bfloat162*)&Hl[base0 + d] = l0;
            *(__nv_bfloat162*)&Hh[base1 + d] = h1;
            *(__nv_bfloat162*)&Hl[base1 + d] = l1;
        }
    }
}

// ---------------------------------------------------------------------------
// Kernel 2: flash attention (R6-passing mainloop; S-GEMM operand fetches
// converted from scalar LDS to ldmatrix.x4 — identical fragment elements).
// ---------------------------------------------------------------------------
#define QW 68
#define VW 136
#define PW 68
#define SM_QH 0
#define SM_QL (128 * QW)
#define SM_KH (SM_QL + 128 * QW)
#define SM_KL (SM_KH + 64 * QW)
#define SM_VS (SM_KL + 64 * QW)
#define SM_PS (SM_VS + 64 * VW)
#define ATTN_WORDS (SM_PS + 128 * PW)
#define ATTN_SMEM (ATTN_WORDS * 4)

__global__ void __launch_bounds__(256, 1) attn_kernel() {
    extern __shared__ float sm[];
    uint32_t* Qh = (uint32_t*)sm + SM_QH;
    uint32_t* Ql = (uint32_t*)sm + SM_QL;
    uint32_t* Kh = (uint32_t*)sm + SM_KH;
    uint32_t* Kl = (uint32_t*)sm + SM_KL;
    float*    Vs = sm + SM_VS;
    float*    Ps = sm + SM_PS;

    const uint32_t sb  = smem_u32(sm);
    const uint32_t bQH = sb + SM_QH * 4;
    const uint32_t bQL = sb + SM_QL * 4;
    const uint32_t bKH = sb + SM_KH * 4;
    const uint32_t bKL = sb + SM_KL * 4;

    const int b  = blockIdx.y;
    const int q0 = blockIdx.x * 128;
    const uint32_t* Qgh = (const uint32_t*)(g_Qh + ((size_t)b * Nn + q0) * Ddim);
    const uint32_t* Qgl = (const uint32_t*)(g_Ql + ((size_t)b * Nn + q0) * Ddim);
    const uint32_t* Kgh = (const uint32_t*)(g_Kh + (size_t)b * Nn * Ddim);
    const uint32_t* Kgl = (const uint32_t*)(g_Kl + (size_t)b * Nn * Ddim);
    const float*    Vg  = g_V + (size_t)b * Nn * Ddim;

    const int tid  = threadIdx.x;
    const int lane = tid & 31;
    const int w    = tid >> 5;
    const int g    = lane >> 2;
    const int t    = lane & 3;

    // ldmatrix per-thread address offsets (bytes)
    const uint32_t aOff = ((uint32_t)(w * 16 + (lane & 7) + ((lane >> 3) & 1) * 8) * QW
                          + (lane >> 4) * 4) * 4;
    const uint32_t bOff = ((uint32_t)((lane >> 4) * 8 + (lane & 7)) * QW
                          + ((lane >> 3) & 1) * 4) * 4;

    #pragma unroll
    for (int i = 0; i < 8; i++) {
        int f = tid + i * 256;
        int r = f >> 4, cw = (f & 15) * 4;
        *(uint4*)&Qh[r * QW + cw] = *(const uint4*)&Qgh[r * 64 + cw];
        *(uint4*)&Ql[r * QW + cw] = *(const uint4*)&Qgl[r * 64 + cw];
    }

    float m0 = -1e30f, m1 = -1e30f, l0 = 0.f, l1 = 0.f;
    float o[16][4];
    #pragma unroll
    for (int nb = 0; nb < 16; nb++)
        #pragma unroll
        for (int c = 0; c < 4; c++) o[nb][c] = 0.f;

    const int row0 = w * 16 + g;
    const int row1 = row0 + 8;

    for (int j0 = 0; j0 < Nn; j0 += 64) {
        __syncthreads();
        #pragma unroll
        for (int i = 0; i < 4; i++) {
            int f = tid + i * 256;
            int r = f >> 4, cw = (f & 15) * 4;
            *(uint4*)&Kh[r * QW + cw] = *(const uint4*)&Kgh[(size_t)(j0 + r) * 64 + cw];
            *(uint4*)&Kl[r * QW + cw] = *(const uint4*)&Kgl[(size_t)(j0 + r) * 64 + cw];
        }
        #pragma unroll
        for (int i = 0; i < 8; i++) {
            int f = tid + i * 256;
            int r = f >> 5, c4 = (f & 31) * 4;
            *(float4*)&Vs[r * VW + c4] = *(const float4*)&Vg[(size_t)(j0 + r) * Ddim + c4];
        }
        __syncthreads();

        // ---- S = Q K^T via ldmatrix fragments (identical elements) ----
        float s[8][4];
        #pragma unroll
        for (int nb = 0; nb < 8; nb++)
            #pragma unroll
            for (int c = 0; c < 4; c++) s[nb][c] = 0.f;

        #pragma unroll
        for (int kb = 0; kb < 8; kb++) {
            const uint32_t kByte = kb * 32;
            uint32_t ah[4], al[4];
            ldsm4(ah, bQH + aOff + kByte);
            ldsm4(al, bQL + aOff + kByte);
            #pragma unroll
            for (int nbp = 0; nbp < 4; nbp++) {
                const uint32_t bo = bOff + (uint32_t)nbp * 16 * QW * 4 + kByte;
                uint32_t bh[4], bl[4];
                ldsm4(bh, bKH + bo);
                ldsm4(bl, bKL + bo);
                mma16(s[2 * nbp],     ah, &bh[0]);
                mma16(s[2 * nbp],     ah, &bl[0]);
                mma16(s[2 * nbp],     al, &bh[0]);
                mma16(s[2 * nbp + 1], ah, &bh[2]);
                mma16(s[2 * nbp + 1], ah, &bl[2]);
                mma16(s[2 * nbp + 1], al, &bh[2]);
            }
        }

        // ---- online softmax (unchanged) ----
        float mx0 = -1e30f, mx1 = -1e30f;
        #pragma unroll
        for (int nb = 0; nb < 8; nb++) {
            mx0 = fmaxf(mx0, fmaxf(s[nb][0], s[nb][1]));
            mx1 = fmaxf(mx1, fmaxf(s[nb][2], s[nb][3]));
        }
        mx0 = fmaxf(mx0, __shfl_xor_sync(0xffffffffu, mx0, 1));
        mx0 = fmaxf(mx0, __shfl_xor_sync(0xffffffffu, mx0, 2));
        mx1 = fmaxf(mx1, __shfl_xor_sync(0xffffffffu, mx1, 1));
        mx1 = fmaxf(mx1, __shfl_xor_sync(0xffffffffu, mx1, 2));
        float mn0 = fmaxf(m0, mx0), mn1 = fmaxf(m1, mx1);
        float sc0 = __expf(m0 - mn0), sc1 = __expf(m1 - mn1);
        m0 = mn0; m1 = mn1;
        l0 *= sc0; l1 *= sc1;
        #pragma unroll
        for (int nb = 0; nb < 16; nb++) {
            o[nb][0] *= sc0; o[nb][1] *= sc0;
            o[nb][2] *= sc1; o[nb][3] *= sc1;
        }
        float rs0 = 0.f, rs1 = 0.f;
        #pragma unroll
        for (int nb = 0; nb < 8; nb++) {
            float p0 = __expf(s[nb][0] - mn0);
            float p1 = __expf(s[nb][1] - mn0);
            float p2 = __expf(s[nb][2] - mn1);
            float p3 = __expf(s[nb][3] - mn1);
            rs0 += p0 + p1;
            rs1 += p2 + p3;
            float2 hi = make_float2(__uint_as_float(f2tf(p0)), __uint_as_float(f2tf(p1)));
            float2 lo = make_float2(__uint_as_float(f2tf(p2)), __uint_as_float(f2tf(p3)));
            *(float2*)&Ps[row0 * PW + nb * 8 + t * 2] = hi;
            *(float2*)&Ps[row1 * PW + nb * 8 + t * 2] = lo;
        }
        rs0 += __shfl_xor_sync(0xffffffffu, rs0, 1);
        rs0 += __shfl_xor_sync(0xffffffffu, rs0, 2);
        rs1 += __shfl_xor_sync(0xffffffffu, rs1, 1);
        rs1 += __shfl_xor_sync(0xffffffffu, rs1, 2);
        l0 += rs0; l1 += rs1;
        __syncwarp();

        // ---- O += P V (tf32, unchanged) ----
        #pragma unroll
        for (int kb = 0; kb < 8; kb++) {
            const int kc = kb * 8 + t;
            uint32_t pa[4];
            pa[0] = __float_as_uint(Ps[row0 * PW + kc]);
            pa[1] = __float_as_uint(Ps[row1 * PW + kc]);
            pa[2] = __float_as_uint(Ps[row0 * PW + kc + 4]);
            pa[3] = __float_as_uint(Ps[row1 * PW + kc + 4]);
            #pragma unroll
            for (int nb = 0; nb < 16; nb++) {
                uint32_t vb[2];
                vb[0] = __float_as_uint(Vs[(kb * 8 + t) * VW + nb * 8 + g]);
                vb[1] = __float_as_uint(Vs[(kb * 8 + t + 4) * VW + nb * 8 + g]);
                mma8(o[nb], pa, vb);
            }
        }
    }

    // Normalize and write Y as bf16 hi/lo split
    float inv0 = 1.f / l0, inv1 = 1.f / l1;
    const size_t base0 = ((size_t)b * Nn + q0 + row0) * Ddim;
    const size_t base1 = ((size_t)b * Nn + q0 + row1) * Ddim;
    #pragma unroll
    for (int nb = 0; nb < 16; nb++) {
        const int d = nb * 8 + t * 2;
        float y00 = o[nb][0] * inv0, y01 = o[nb][1] * inv0;
        float y10 = o[nb][2] * inv1, y11 = o[nb][3] * inv1;
        __nv_bfloat162 h0, l0v, h1, l1v;
        h0.x = __float2bfloat16_rn(y00);
        h0.y = __float2bfloat16_rn(y01);
        l0v.x = __float2bfloat16_rn(y00 - __bfloat162float(h0.x));
        l0v.y = __float2bfloat16_rn(y01 - __bfloat162float(h0.y));
        h1.x = __float2bfloat16_rn(y10);
        h1.y = __float2bfloat16_rn(y11);
        l1v.x = __float2bfloat16_rn(y10 - __bfloat162float(h1.x));
        l1v.y = __float2bfloat16_rn(y11 - __bfloat162float(h1.y));
        *(__nv_bfloat162*)&g_Yh[base0 + d] = h0;
        *(__nv_bfloat162*)&g_Yl[base0 + d] = l0v;
        *(__nv_bfloat162*)&g_Yh[base1 + d] = h1;
        *(__nv_bfloat162*)&g_Yl[base1 + d] = l1v;
    }
}

// ---------------------------------------------------------------------------
// Kernel 3: out = x + w_out * y on tensor cores (unchanged from R6 pass).
// ---------------------------------------------------------------------------
#define OUT_AH 0
#define OUT_AL (128 * P36)
#define OUT_BH (2 * 128 * P36)
#define OUT_BL (2 * 128 * P36 + 64 * P36)
#define OUT_SMEM ((2 * 128 * P36 + 2 * 64 * P36) * 4)

__global__ void __launch_bounds__(256) out_tc_kernel(const float* __restrict__ x,
                                                     float* __restrict__ out) {
    extern __shared__ uint32_t S[];
    const int b = blockIdx.z, c0 = blockIdx.y * 128, n0 = blockIdx.x * 64;
    const int tid = threadIdx.x;
    const int lane = tid & 31, w = tid >> 5;
    const int g = lane >> 2, t = lane & 3;
    const int row0 = w * 16 + g, row1 = row0 + 8;

    const uint32_t* Ahw = (const uint32_t*)(g_Wh + 3 * 32768);
    const uint32_t* Alw = (const uint32_t*)(g_Wl + 3 * 32768);
    const uint32_t* Bhw = (const uint32_t*)g_Yh;
    const uint32_t* Blw = (const uint32_t*)g_Yl;

    float acc[8][4];
    #pragma unroll
    for (int nb = 0; nb < 8; nb++)
        #pragma unroll
        for (int c = 0; c < 4; c++) acc[nb][c] = 0.f;

    for (int chunk = 0; chunk < 2; chunk++) {
        const int dd0 = chunk * 64;
        __syncthreads();
        #pragma unroll
        for (int i = 0; i < 4; i++) {
            int f = tid + i * 256;
            int r = f >> 3, w4 = (f & 7) * 4;
            int ab = (c0 + r) * 64 + (dd0 >> 1);
            *(uint4*)&S[OUT_AH + r * P36 + w4] = *(const uint4*)&Ahw[ab + w4];
            *(uint4*)&S[OUT_AL + r * P36 + w4] = *(const uint4*)&Alw[ab + w4];
        }
        #pragma unroll
        for (int i = 0; i < 2; i++) {
            int f = tid + i * 256;
            int r = f >> 3, w4 = (f & 7) * 4;
            size_t bb = ((size_t)(b * Nn + n0 + r) * Ddim + dd0) >> 1;
            *(uint4*)&S[OUT_BH + r * P36 + w4] = *(const uint4*)&Bhw[bb + w4];
            *(uint4*)&S[OUT_BL + r * P36 + w4] = *(const uint4*)&Blw[bb + w4];
        }
        __syncthreads();

        #pragma unroll
        for (int kb = 0; kb < 4; kb++) {
            const int kw = kb * 8 + t;
            uint32_t ah[4], al[4];
            ah[0] = S[OUT_AH + row0 * P36 + kw];
            ah[1] = S[OUT_AH + row1 * P36 + kw];
            ah[2] = S[OUT_AH + row0 * P36 + kw + 4];
            ah[3] = S[OUT_AH + row1 * P36 + kw + 4];
            al[0] = S[OUT_AL + row0 * P36 + kw];
            al[1] = S[OUT_AL + row1 * P36 + kw];
            al[2] = S[OUT_AL + row0 * P36 + kw + 4];
            al[3] = S[OUT_AL + row1 * P36 + kw + 4];
            #pragma unroll
            for (int nb = 0; nb < 8; nb++) {
                const int rr = nb * 8 + g;
                uint32_t bh[2], bl[2];
                bh[0] = S[OUT_BH + rr * P36 + kw];
                bh[1] = S[OUT_BH + rr * P36 + kw + 4];
                bl[0] = S[OUT_BL + rr * P36 + kw];
                bl[1] = S[OUT_BL + rr * P36 + kw + 4];
                mma16(acc[nb], ah, bh);
                mma16(acc[nb], ah, bl);
                mma16(acc[nb], al, bh);
            }
        }
    }

    const int ch0 = c0 + row0, ch1 = c0 + row1;
    #pragma unroll
    for (int nb = 0; nb < 8; nb++) {
        const int pix = n0 + nb * 8 + t * 2;
        size_t i0 = (size_t)b * Cdim * Nn + (size_t)ch0 * Nn + pix;
        size_t i1 = (size_t)b * Cdim * Nn + (size_t)ch1 * Nn + pix;
        float2 x0 = *(const float2*)&x[i0];
        float2 x1 = *(const float2*)&x[i1];
        *(float2*)&out[i0] = make_float2(x0.x + acc[nb][0], x0.y + acc[nb][1]);
        *(float2*)&out[i1] = make_float2(x1.x + acc[nb][2], x1.y + acc[nb][3]);
    }
}

// ---------------------------------------------------------------------------
extern "C" void kernel_launch(void* const* d_in, const int* in_sizes, int n_in,
                              void* d_out, int out_size) {
    const float* x  = (const float*)d_in[0];
    const float* wt = (const float*)d_in[1];
    const float* wp = (const float*)d_in[2];
    const float* wg = (const float*)d_in[3];
    const float* wo = (const float*)d_in[4];
    float* out = (float*)d_out;

    cudaFuncSetAttribute(attn_kernel,
                         cudaFuncAttributeMaxDynamicSharedMemorySize, ATTN_SMEM);
    cudaFuncSetAttribute(qkv_tc_kernel,
                         cudaFuncAttributeMaxDynamicSharedMemorySize, QKV_SMEM);
    cudaFuncSetAttribute(out_tc_kernel,
                         cudaFuncAttributeMaxDynamicSharedMemorySize, OUT_SMEM);

    split_w4_kernel<<<dim3(128, 4), 256>>>(wt, wp, wg, wo);
    xpose_kernel<<<dim3(Nn / 32, Cdim / 32, Bsz), 256>>>(x);
    qkv_tc_kernel<<<dim3(Nn / 128, 3, Bsz), 256, QKV_SMEM>>>();
    attn_kernel<<<dim3(Nn / 128, Bsz), 256, ATTN_SMEM>>>();
    out_tc_kernel<<<dim3(Nn / 64, Cdim / 128, Bsz), 256, OUT_SMEM>>>(x, out);
}